// round 2
// baseline (speedup 1.0000x reference)
#include <cuda_runtime.h>
#include <math.h>

#define NN 50000
#define NE 800000
#define BGR 256
#define HD 128
#define NHF (NN * HD)
#define BH (BGR * HD)

// ---------------- device scratch ----------------
__device__ __align__(16) float g_agg[NHF];
__device__ __align__(16) float g_tmp[NHF];
__device__ __align__(16) float g_feat[NHF];
__device__ int g_cnt[NN];
__device__ int g_rowstart[NN + 1];
__device__ int g_cursor[NN];
__device__ int g_eidsrc[NE];
__device__ __align__(16) float g_stats[4 * 512];
__device__ __align__(16) float g_h[2 * 4 * BH];
__device__ __align__(16) float g_c[2 * 4 * BH];
__device__ __align__(16) float g_qstar[BGR * 2 * HD];
__device__ float g_e[NN];
__device__ unsigned g_m[4 * BGR];
__device__ float g_s[4 * BGR];
__device__ __align__(16) float g_rnum[4 * BH];

__device__ __forceinline__ unsigned fenc(float f) {
    int i = __float_as_int(f);
    return (i >= 0) ? ((unsigned)i | 0x80000000u) : (unsigned)(~i);
}
__device__ __forceinline__ float fdec(unsigned u) {
    return (u & 0x80000000u) ? __int_as_float((int)(u & 0x7fffffffu))
                             : __int_as_float(~(int)u);
}

// ---------------- init ----------------
__global__ void k_zero() {
    int i0 = blockIdx.x * blockDim.x + threadIdx.x;
    int st = gridDim.x * blockDim.x;
    for (int i = i0; i < NN; i += st) g_cnt[i] = 0;
    for (int i = i0; i < 4 * 512; i += st) g_stats[i] = 0.f;
    for (int i = i0; i < 2 * 4 * BH; i += st) { g_h[i] = 0.f; g_c[i] = 0.f; }
    for (int i = i0; i < 4 * BH; i += st) g_rnum[i] = 0.f;
    for (int i = i0; i < BGR * 2 * HD; i += st) g_qstar[i] = 0.f;
    for (int i = i0; i < 4 * BGR; i += st) { g_m[i] = 0u; g_s[i] = 0.f; }
}

// ---------------- CSR build ----------------
__global__ void k_hist(const int* __restrict__ ei) {
    int i = blockIdx.x * blockDim.x + threadIdx.x;
    if (i < NE) atomicAdd(&g_cnt[ei[NE + i]], 1);
}

__global__ void k_scan() {
    __shared__ int wsum[32];
    __shared__ int carry_sh, tile_sh;
    int tid = threadIdx.x, lane = tid & 31, wid = tid >> 5;
    if (tid == 0) carry_sh = 0;
    __syncthreads();
    for (int base = 0; base < NN; base += 1024) {
        int idx = base + tid;
        int v = (idx < NN) ? g_cnt[idx] : 0;
        int incl = v;
#pragma unroll
        for (int off = 1; off < 32; off <<= 1) {
            int t = __shfl_up_sync(0xffffffffu, incl, off);
            if (lane >= off) incl += t;
        }
        if (lane == 31) wsum[wid] = incl;
        __syncthreads();
        if (wid == 0) {
            int wv = wsum[lane];
            int wincl = wv;
#pragma unroll
            for (int off = 1; off < 32; off <<= 1) {
                int t = __shfl_up_sync(0xffffffffu, wincl, off);
                if (lane >= off) wincl += t;
            }
            wsum[lane] = wincl - wv;
            if (lane == 31) tile_sh = wincl;
        }
        __syncthreads();
        if (idx < NN) g_rowstart[idx] = carry_sh + wsum[wid] + incl - v;
        __syncthreads();
        if (tid == 0) carry_sh += tile_sh;
        __syncthreads();
    }
    if (tid == 0) g_rowstart[NN] = carry_sh;
}

__global__ void k_copycur() {
    int i = blockIdx.x * blockDim.x + threadIdx.x;
    if (i < NN) g_cursor[i] = g_rowstart[i];
}

__global__ void k_scatter(const int* __restrict__ ei) {
    int i = blockIdx.x * blockDim.x + threadIdx.x;
    if (i < NE) {
        int pos = atomicAdd(&g_cursor[ei[NE + i]], 1);
        g_eidsrc[pos] = ei[i];
    }
}

// out[n] = x[n] + sum_{j->n} x[j]
__global__ void k_gather(const float* __restrict__ xin, float* __restrict__ out) {
    int gw = (blockIdx.x * blockDim.x + threadIdx.x) >> 5;
    int lane = threadIdx.x & 31;
    if (gw >= NN) return;
    const float4* x4 = (const float4*)xin;
    float4 acc = x4[(size_t)gw * 32 + lane];
    int s1 = g_rowstart[gw + 1];
    for (int j = g_rowstart[gw]; j < s1; j++) {
        float4 v = __ldg(&x4[(size_t)g_eidsrc[j] * 32 + lane]);
        acc.x += v.x; acc.y += v.y; acc.z += v.z; acc.w += v.w;
    }
    ((float4*)out)[(size_t)gw * 32 + lane] = acc;
}

// ---------------- GEMM: C[M,128] = A[M,128] @ W^T + b ----------------
__global__ void __launch_bounds__(256) k_gemm(const float* __restrict__ A,
                                              const float* __restrict__ W,
                                              const float* __restrict__ bias,
                                              float* __restrict__ C, int M) {
    __shared__ float Ash[16][132];
    __shared__ float Wsh[16][132];
    int m0 = blockIdx.x * 128;
    int t = threadIdx.x, ty = t >> 4, tx = t & 15;
    float acc[8][8];
#pragma unroll
    for (int i = 0; i < 8; i++)
#pragma unroll
        for (int j = 0; j < 8; j++) acc[i][j] = 0.f;

    for (int k0 = 0; k0 < 128; k0 += 16) {
#pragma unroll
        for (int u = 0; u < 2; u++) {
            int e = t + u * 256;
            int r = e >> 2, j = (e & 3) << 2;
            int m = m0 + r;
            float4 av = make_float4(0.f, 0.f, 0.f, 0.f);
            if (m < M) av = __ldg((const float4*)(A + (size_t)m * HD + k0 + j));
            Ash[j + 0][r] = av.x; Ash[j + 1][r] = av.y;
            Ash[j + 2][r] = av.z; Ash[j + 3][r] = av.w;
            float4 wv = __ldg((const float4*)(W + (size_t)r * HD + k0 + j));
            Wsh[j + 0][r] = wv.x; Wsh[j + 1][r] = wv.y;
            Wsh[j + 2][r] = wv.z; Wsh[j + 3][r] = wv.w;
        }
        __syncthreads();
#pragma unroll
        for (int kk = 0; kk < 16; kk++) {
            float a[8], b[8];
            *(float4*)(a)     = *(const float4*)&Ash[kk][ty * 8];
            *(float4*)(a + 4) = *(const float4*)&Ash[kk][ty * 8 + 4];
            *(float4*)(b)     = *(const float4*)&Wsh[kk][tx * 8];
            *(float4*)(b + 4) = *(const float4*)&Wsh[kk][tx * 8 + 4];
#pragma unroll
            for (int i = 0; i < 8; i++)
#pragma unroll
                for (int j = 0; j < 8; j++) acc[i][j] += a[i] * b[j];
        }
        __syncthreads();
    }
    float bv[8];
#pragma unroll
    for (int j = 0; j < 8; j++) bv[j] = __ldg(bias + tx * 8 + j);
#pragma unroll
    for (int i = 0; i < 8; i++) {
        int m = m0 + ty * 8 + i;
        if (m < M) {
            float4 o0 = make_float4(acc[i][0] + bv[0], acc[i][1] + bv[1],
                                    acc[i][2] + bv[2], acc[i][3] + bv[3]);
            float4 o1 = make_float4(acc[i][4] + bv[4], acc[i][5] + bv[5],
                                    acc[i][6] + bv[6], acc[i][7] + bv[7]);
            *(float4*)(C + (size_t)m * HD + tx * 8) = o0;
            *(float4*)(C + (size_t)m * HD + tx * 8 + 4) = o1;
        }
    }
}

// ---------------- batchnorm ----------------
__global__ void k_colstats(const float* __restrict__ in, float* __restrict__ stat, int M) {
    int c = threadIdx.x;
    float s = 0.f, q = 0.f;
    for (int r = blockIdx.x; r < M; r += gridDim.x) {
        float v = in[(size_t)r * HD + c];
        s += v; q += v * v;
    }
    atomicAdd(&stat[c], s);
    atomicAdd(&stat[128 + c], q);
}

__global__ void k_bnfin(float* __restrict__ stat, const float* __restrict__ gamma,
                        const float* __restrict__ beta, int M) {
    int c = threadIdx.x;
    float mean = stat[c] / (float)M;
    float var = stat[128 + c] / (float)M - mean * mean;
    float sc = gamma[c] * rsqrtf(var + 1e-5f);
    stat[256 + c] = sc;
    stat[384 + c] = beta[c] - mean * sc;
}

__global__ void k_bnrelu(const float* __restrict__ in, const float* __restrict__ stat,
                         float* __restrict__ out, int M) {
    int i = blockIdx.x * blockDim.x + threadIdx.x;
    if (i >= M * 32) return;
    int c = (i & 31) * 4;
    float4 v = ((const float4*)in)[i];
    v.x = fmaxf(0.f, v.x * __ldg(stat + 256 + c + 0) + __ldg(stat + 384 + c + 0));
    v.y = fmaxf(0.f, v.y * __ldg(stat + 256 + c + 1) + __ldg(stat + 384 + c + 1));
    v.z = fmaxf(0.f, v.z * __ldg(stat + 256 + c + 2) + __ldg(stat + 384 + c + 2));
    v.w = fmaxf(0.f, v.w * __ldg(stat + 256 + c + 3) + __ldg(stat + 384 + c + 3));
    ((float4*)out)[i] = v;
}

// ---------------- fused LSTM cell ----------------
__global__ void __launch_bounds__(256) k_lstm(const float* __restrict__ X, int D,
                                              const float* __restrict__ hprev,
                                              const float* __restrict__ Wih,
                                              const float* __restrict__ Whh,
                                              const float* __restrict__ bias,
                                              const float* __restrict__ cprev,
                                              float* __restrict__ hout,
                                              float* __restrict__ cout) {
    __shared__ float Xs[32][16];
    __shared__ float Ws[32][68];
    int m0 = blockIdx.x * 16, c0 = blockIdx.y * 16;
    int t = threadIdx.x, ty = t >> 4, tx = t & 15;
    float acc[4] = {0.f, 0.f, 0.f, 0.f};
    int total = D + 128;
    for (int k0 = 0; k0 < total; k0 += 32) {
        const float* src; int sstride, kb;
        const float* w; int wstride;
        if (k0 < D) { src = X; sstride = D; kb = k0; w = Wih; wstride = D; }
        else { src = hprev; sstride = 128; kb = k0 - D; w = Whh; wstride = 128; }
#pragma unroll
        for (int u = 0; u < 2; u++) {
            int e = t + u * 256;
            int kk = e >> 4, mm = e & 15;
            Xs[kk][mm] = __ldg(src + (size_t)(m0 + mm) * sstride + kb + kk);
        }
#pragma unroll
        for (int u = 0; u < 8; u++) {
            int e = t + u * 256;
            int kk = e >> 6, nn = e & 63;
            int gg = nn >> 4, ci = nn & 15;
            Ws[kk][nn] = __ldg(w + (size_t)(gg * 128 + c0 + ci) * wstride + kb + kk);
        }
        __syncthreads();
#pragma unroll 8
        for (int kk = 0; kk < 32; kk++) {
            float a = Xs[kk][ty];
            acc[0] += a * Ws[kk][tx];
            acc[1] += a * Ws[kk][16 + tx];
            acc[2] += a * Ws[kk][32 + tx];
            acc[3] += a * Ws[kk][48 + tx];
        }
        __syncthreads();
    }
    int b = m0 + ty, c = c0 + tx;
    float gi = acc[0] + __ldg(bias + c);
    float gf = acc[1] + __ldg(bias + 128 + c);
    float gc = acc[2] + __ldg(bias + 256 + c);
    float go = acc[3] + __ldg(bias + 384 + c);
    int idx = b * HD + c;
    float si = 1.f / (1.f + __expf(-gi));
    float sf = 1.f / (1.f + __expf(-gf));
    float so = 1.f / (1.f + __expf(-go));
    float cn = sf * cprev[idx] + si * tanhf(gc);
    cout[idx] = cn;
    hout[idx] = so * tanhf(cn);
}

// ---------------- attention ----------------
__global__ void k_attn_e(const float* __restrict__ xf, const float* __restrict__ q,
                         const int* __restrict__ batch, unsigned* __restrict__ marr) {
    int gw = (blockIdx.x * blockDim.x + threadIdx.x) >> 5;
    int lane = threadIdx.x & 31;
    int n0 = gw * 16;
    if (n0 >= NN) return;
    int n1 = min(n0 + 16, NN);
    const float4* x4 = (const float4*)xf;
    const float4* q4 = (const float4*)q;
    int runb = -1; float runmax = 0.f;
    for (int n = n0; n < n1; n++) {
        int b = __ldg(batch + n);
        float4 xv = x4[(size_t)n * 32 + lane];
        float4 qv = __ldg(&q4[(size_t)b * 32 + lane]);
        float d = xv.x * qv.x + xv.y * qv.y + xv.z * qv.z + xv.w * qv.w;
#pragma unroll
        for (int off = 16; off; off >>= 1) d += __shfl_xor_sync(0xffffffffu, d, off);
        if (lane == 0) g_e[n] = d;
        if (b != runb) {
            if (runb >= 0 && lane == 0) atomicMax(marr + runb, fenc(runmax));
            runb = b; runmax = d;
        } else runmax = fmaxf(runmax, d);
    }
    if (runb >= 0 && lane == 0) atomicMax(marr + runb, fenc(runmax));
}

__global__ void k_attn_r(const float* __restrict__ xf, const int* __restrict__ batch,
                         const unsigned* __restrict__ marr,
                         float* __restrict__ rnum, float* __restrict__ sarr) {
    int gw = (blockIdx.x * blockDim.x + threadIdx.x) >> 5;
    int lane = threadIdx.x & 31;
    int n0 = gw * 64;
    if (n0 >= NN) return;
    int n1 = min(n0 + 64, NN);
    const float4* x4 = (const float4*)xf;
    float4 acc = make_float4(0.f, 0.f, 0.f, 0.f);
    float se = 0.f;
    int runb = -1; float mb = 0.f;
    for (int n = n0; n < n1; n++) {
        int b = __ldg(batch + n);
        if (b != runb) {
            if (runb >= 0) {
                float* dst = rnum + (size_t)runb * HD + lane * 4;
                atomicAdd(dst + 0, acc.x); atomicAdd(dst + 1, acc.y);
                atomicAdd(dst + 2, acc.z); atomicAdd(dst + 3, acc.w);
                if (lane == 0) atomicAdd(sarr + runb, se);
                acc = make_float4(0.f, 0.f, 0.f, 0.f); se = 0.f;
            }
            runb = b;
            mb = fdec(__ldg(marr + b));
        }
        float ee = __expf(g_e[n] - mb);
        float4 xv = x4[(size_t)n * 32 + lane];
        acc.x += ee * xv.x; acc.y += ee * xv.y;
        acc.z += ee * xv.z; acc.w += ee * xv.w;
        se += ee;
    }
    if (runb >= 0) {
        float* dst = rnum + (size_t)runb * HD + lane * 4;
        atomicAdd(dst + 0, acc.x); atomicAdd(dst + 1, acc.y);
        atomicAdd(dst + 2, acc.z); atomicAdd(dst + 3, acc.w);
        if (lane == 0) atomicAdd(sarr + runb, se);
    }
}

__global__ void k_attn_fin(const float* __restrict__ q, const float* __restrict__ rnum,
                           const float* __restrict__ sarr, float* __restrict__ qstar) {
    int idx = blockIdx.x * blockDim.x + threadIdx.x;
    if (idx >= BGR * 2 * HD) return;
    int b = idx >> 8, c = idx & 255;
    float v;
    if (c < 128) v = q[b * HD + c];
    else {
        float s = sarr[b];
        v = (s > 0.f) ? rnum[b * HD + (c - 128)] / s : 0.f;
    }
    qstar[idx] = v;
}

// ---------------- final linear ----------------
__global__ void k_final(const float* __restrict__ qstar, const float* __restrict__ linW,
                        const float* __restrict__ linb, float* __restrict__ out) {
    int gw = (blockIdx.x * blockDim.x + threadIdx.x) >> 5;   // 0..511 = b*2+o
    int lane = threadIdx.x & 31;
    if (gw >= BGR * 2) return;
    int b = gw >> 1, o = gw & 1;
    const float4* q4 = (const float4*)(qstar + b * 256);
    const float4* w4 = (const float4*)(linW + o * 256);
    float d = 0.f;
#pragma unroll
    for (int u = 0; u < 2; u++) {
        float4 a = q4[lane + u * 32];
        float4 w = __ldg(&w4[lane + u * 32]);
        d += a.x * w.x + a.y * w.y + a.z * w.z + a.w * w.w;
    }
#pragma unroll
    for (int off = 16; off; off >>= 1) d += __shfl_xor_sync(0xffffffffu, d, off);
    if (lane == 0) out[b * 2 + o] = d + __ldg(linb + o);
}

// ---------------- host ----------------
static float* symf(const void* sym) {
    void* p = nullptr;
    cudaGetSymbolAddress(&p, sym);
    return (float*)p;
}

extern "C" void kernel_launch(void* const* d_in, const int* in_sizes, int n_in,
                              void* d_out, int out_size) {
    const float* x     = (const float*)d_in[0];
    const int*   ei    = (const int*)d_in[1];
    const int*   batch = (const int*)d_in[2];
    const float* gW1[2] = {(const float*)d_in[3],  (const float*)d_in[11]};
    const float* gb1[2] = {(const float*)d_in[4],  (const float*)d_in[12]};
    const float* gg1[2] = {(const float*)d_in[5],  (const float*)d_in[13]};
    const float* ge1[2] = {(const float*)d_in[6],  (const float*)d_in[14]};
    const float* gW2[2] = {(const float*)d_in[7],  (const float*)d_in[15]};
    const float* gb2[2] = {(const float*)d_in[8],  (const float*)d_in[16]};
    const float* gg2[2] = {(const float*)d_in[9],  (const float*)d_in[17]};
    const float* ge2[2] = {(const float*)d_in[10], (const float*)d_in[18]};
    const float* Wih0 = (const float*)d_in[19];
    const float* Whh0 = (const float*)d_in[20];
    const float* b0   = (const float*)d_in[21];
    const float* WihR = (const float*)d_in[22];
    const float* WhhR = (const float*)d_in[23];
    const float* bR   = (const float*)d_in[24];
    const float* linW = (const float*)d_in[25];
    const float* linb = (const float*)d_in[26];
    float* out = (float*)d_out;

    float* agg   = symf(g_agg);
    float* tmp   = symf(g_tmp);
    float* feat  = symf(g_feat);
    float* stats = symf(g_stats);
    float* hbuf  = symf(g_h);
    float* cbuf  = symf(g_c);
    float* qstar = symf(g_qstar);
    void* pm = nullptr; cudaGetSymbolAddress(&pm, g_m);
    unsigned* marr = (unsigned*)pm;
    float* sarr  = symf(g_s);
    float* rnum  = symf(g_rnum);

    k_zero<<<256, 256>>>();
    k_hist<<<(NE + 255) / 256, 256>>>(ei);
    k_scan<<<1, 1024>>>();
    k_copycur<<<(NN + 255) / 256, 256>>>();
    k_scatter<<<(NE + 255) / 256, 256>>>(ei);

    int gemmBlocks = (NN + 127) / 128;
    int bnBlocks = (NN * 32 + 255) / 256;
    int gatherBlocks = (NN * 32 + 255) / 256;

    const float* layerIn = x;
    for (int l = 0; l < 2; l++) {
        k_gather<<<gatherBlocks, 256>>>(layerIn, agg);
        float* st1 = stats + (l * 2 + 0) * 512;
        float* st2 = stats + (l * 2 + 1) * 512;
        k_gemm<<<gemmBlocks, 256>>>(agg, gW1[l], gb1[l], tmp, NN);
        k_colstats<<<256, 128>>>(tmp, st1, NN);
        k_bnfin<<<1, 128>>>(st1, gg1[l], ge1[l], NN);
        k_bnrelu<<<bnBlocks, 256>>>(tmp, st1, tmp, NN);
        k_gemm<<<gemmBlocks, 256>>>(tmp, gW2[l], gb2[l], agg, NN);
        k_colstats<<<256, 128>>>(agg, st2, NN);
        k_bnfin<<<1, 128>>>(st2, gg2[l], ge2[l], NN);
        k_bnrelu<<<bnBlocks, 256>>>(agg, st2, feat, NN);
        layerIn = feat;
    }

    dim3 lstmGrid(BGR / 16, HD / 16);
    int attnEBlocks = ((NN + 15) / 16 * 32 + 255) / 256;
    int attnRBlocks = ((NN + 63) / 64 * 32 + 255) / 256;

    for (int s = 0; s < 4; s++) {
        int p = s & 1;
        float* hOld = hbuf + p * 4 * BH;
        float* hNew = hbuf + (p ^ 1) * 4 * BH;
        float* cOld = cbuf + p * 4 * BH;
        float* cNew = cbuf + (p ^ 1) * 4 * BH;
        for (int l = 0; l < 4; l++) {
            const float* X = (l == 0) ? qstar : (hNew + (l - 1) * BH);
            int D = (l == 0) ? 256 : 128;
            const float* Wih = (l == 0) ? Wih0 : (WihR + (size_t)(l - 1) * 512 * 128);
            const float* Whh = (l == 0) ? Whh0 : (WhhR + (size_t)(l - 1) * 512 * 128);
            const float* bb  = (l == 0) ? b0   : (bR + (size_t)(l - 1) * 512);
            k_lstm<<<lstmGrid, 256>>>(X, D, hOld + l * BH, Wih, Whh, bb,
                                      cOld + l * BH, hNew + l * BH, cNew + l * BH);
        }
        const float* q = hNew + 3 * BH;
        k_attn_e<<<attnEBlocks, 256>>>(feat, q, batch, marr + s * BGR);
        k_attn_r<<<attnRBlocks, 256>>>(feat, batch, marr + s * BGR,
                                       rnum + s * BH, sarr + s * BGR);
        k_attn_fin<<<(BGR * 2 * HD + 255) / 256, 256>>>(q, rnum + s * BH,
                                                        sarr + s * BGR, qstar);
    }

    k_final<<<(BGR * 2 * 32 + 255) / 256, 256>>>(qstar, linW, linb, out);
}

// round 3
// speedup vs baseline: 1.0922x; 1.0922x over previous
#include <cuda_runtime.h>
#include <math.h>

#define NN 50000
#define NE 800000
#define BGR 256
#define HD 128
#define NHF (NN * HD)
#define BH (BGR * HD)

// ---------------- device scratch ----------------
__device__ __align__(16) float g_agg[NHF];
__device__ __align__(16) float g_tmp[NHF];
__device__ __align__(16) float g_feat[NHF];
__device__ int g_cnt[NN];
__device__ int g_rowstart[NN + 1];
__device__ int g_cursor[NN];
__device__ int g_eidsrc[NE];
__device__ __align__(16) float g_stats[4 * 512];
__device__ __align__(16) float g_h[2 * 4 * BH];
__device__ __align__(16) float g_c[2 * 4 * BH];
__device__ __align__(16) float g_qstar[BGR * 2 * HD];
__device__ float g_e[NN];
__device__ unsigned g_m[4 * BGR];
__device__ float g_s[4 * BGR];
__device__ __align__(16) float g_rnum[4 * BH];

__device__ __forceinline__ unsigned fenc(float f) {
    int i = __float_as_int(f);
    return (i >= 0) ? ((unsigned)i | 0x80000000u) : (unsigned)(~i);
}
__device__ __forceinline__ float fdec(unsigned u) {
    return (u & 0x80000000u) ? __int_as_float((int)(u & 0x7fffffffu))
                             : __int_as_float(~(int)u);
}

// ---------------- init ----------------
__global__ void k_zero() {
    int i0 = blockIdx.x * blockDim.x + threadIdx.x;
    int st = gridDim.x * blockDim.x;
    for (int i = i0; i < NN; i += st) g_cnt[i] = 0;
    for (int i = i0; i < 4 * 512; i += st) g_stats[i] = 0.f;
    for (int i = i0; i < 2 * 4 * BH; i += st) { g_h[i] = 0.f; g_c[i] = 0.f; }
    for (int i = i0; i < 4 * BH; i += st) g_rnum[i] = 0.f;
    for (int i = i0; i < BGR * 2 * HD; i += st) g_qstar[i] = 0.f;
    for (int i = i0; i < 4 * BGR; i += st) { g_m[i] = 0u; g_s[i] = 0.f; }
}

// ---------------- CSR build ----------------
__global__ void k_hist(const int* __restrict__ ei) {
    int i = blockIdx.x * blockDim.x + threadIdx.x;
    if (i < NE) atomicAdd(&g_cnt[ei[NE + i]], 1);
}

__global__ void k_scan() {
    __shared__ int wsum[32];
    __shared__ int carry_sh, tile_sh;
    int tid = threadIdx.x, lane = tid & 31, wid = tid >> 5;
    if (tid == 0) carry_sh = 0;
    __syncthreads();
    for (int base = 0; base < NN; base += 1024) {
        int idx = base + tid;
        int v = (idx < NN) ? g_cnt[idx] : 0;
        int incl = v;
#pragma unroll
        for (int off = 1; off < 32; off <<= 1) {
            int t = __shfl_up_sync(0xffffffffu, incl, off);
            if (lane >= off) incl += t;
        }
        if (lane == 31) wsum[wid] = incl;
        __syncthreads();
        if (wid == 0) {
            int wv = wsum[lane];
            int wincl = wv;
#pragma unroll
            for (int off = 1; off < 32; off <<= 1) {
                int t = __shfl_up_sync(0xffffffffu, wincl, off);
                if (lane >= off) wincl += t;
            }
            wsum[lane] = wincl - wv;
            if (lane == 31) tile_sh = wincl;
        }
        __syncthreads();
        if (idx < NN) {
            int excl = carry_sh + wsum[wid] + incl - v;
            g_rowstart[idx] = excl;
            g_cursor[idx] = excl;
        }
        __syncthreads();
        if (tid == 0) carry_sh += tile_sh;
        __syncthreads();
    }
    if (tid == 0) g_rowstart[NN] = carry_sh;
}

__global__ void k_scatter(const int* __restrict__ ei) {
    int i = blockIdx.x * blockDim.x + threadIdx.x;
    if (i < NE) {
        int pos = atomicAdd(&g_cursor[ei[NE + i]], 1);
        g_eidsrc[pos] = ei[i];
    }
}

// out[n] = x[n] + sum_{j->n} x[j]   (unroll x4 for MLP)
__global__ void k_gather(const float* __restrict__ xin, float* __restrict__ out) {
    int gw = (blockIdx.x * blockDim.x + threadIdx.x) >> 5;
    int lane = threadIdx.x & 31;
    if (gw >= NN) return;
    const float4* x4 = (const float4*)xin;
    float4 acc = x4[(size_t)gw * 32 + lane];
    int s0 = g_rowstart[gw], s1 = g_rowstart[gw + 1];
    int j = s0;
    for (; j + 4 <= s1; j += 4) {
        int i0 = g_eidsrc[j], i1 = g_eidsrc[j + 1];
        int i2 = g_eidsrc[j + 2], i3 = g_eidsrc[j + 3];
        float4 v0 = __ldg(&x4[(size_t)i0 * 32 + lane]);
        float4 v1 = __ldg(&x4[(size_t)i1 * 32 + lane]);
        float4 v2 = __ldg(&x4[(size_t)i2 * 32 + lane]);
        float4 v3 = __ldg(&x4[(size_t)i3 * 32 + lane]);
        acc.x += (v0.x + v1.x) + (v2.x + v3.x);
        acc.y += (v0.y + v1.y) + (v2.y + v3.y);
        acc.z += (v0.z + v1.z) + (v2.z + v3.z);
        acc.w += (v0.w + v1.w) + (v2.w + v3.w);
    }
    for (; j < s1; j++) {
        float4 v = __ldg(&x4[(size_t)g_eidsrc[j] * 32 + lane]);
        acc.x += v.x; acc.y += v.y; acc.z += v.z; acc.w += v.w;
    }
    ((float4*)out)[(size_t)gw * 32 + lane] = acc;
}

// ---------------- tf32 helpers ----------------
__device__ __forceinline__ void split_tf32(float f, unsigned& hi, unsigned& lo) {
    unsigned h;
    asm("cvt.rna.tf32.f32 %0, %1;" : "=r"(h) : "f"(f));
    float r = f - __uint_as_float(h);
    unsigned l;
    asm("cvt.rna.tf32.f32 %0, %1;" : "=r"(l) : "f"(r));
    hi = h; lo = l;
}

__device__ __forceinline__ void mma8(float4& d, unsigned a0, unsigned a1,
                                     unsigned a2, unsigned a3,
                                     unsigned b0, unsigned b1) {
    asm volatile(
        "mma.sync.aligned.m16n8k8.row.col.f32.tf32.tf32.f32 "
        "{%0,%1,%2,%3},{%4,%5,%6,%7},{%8,%9},{%0,%1,%2,%3};\n"
        : "+f"(d.x), "+f"(d.y), "+f"(d.z), "+f"(d.w)
        : "r"(a0), "r"(a1), "r"(a2), "r"(a3), "r"(b0), "r"(b1));
}

// ---------------- GEMM: C[M,128] = A[M,128] @ W^T + b  (3xTF32 tensor core) ----------------
// Block: 128 rows x 128 cols, 256 threads (8 warps: 2 along M x 4 along N).
// Warp tile: 64x32 = 4 m16 tiles x 4 n8 tiles. K staged through smem in two
// 64-wide chunks, stride 68 floats (conflict-free for frag loads).
#define KCH 64
#define SSTR 68
__global__ void __launch_bounds__(256) k_gemm_tf32(const float* __restrict__ A,
                                                   const float* __restrict__ W,
                                                   const float* __restrict__ bias,
                                                   float* __restrict__ C, int M) {
    extern __shared__ float sm[];
    float* As = sm;                    // [128][68]
    float* Ws = sm + 128 * SSTR;       // [128][68]
    int m0 = blockIdx.x * 128;
    int t = threadIdx.x;
    int wid = t >> 5, lane = t & 31;
    int wm = wid >> 2, wn = wid & 3;       // warp grid 2x4
    int g = lane >> 2, tg = lane & 3;      // mma group / in-group

    float4 acc[4][4];
#pragma unroll
    for (int i = 0; i < 4; i++)
#pragma unroll
        for (int j = 0; j < 4; j++) acc[i][j] = make_float4(0.f, 0.f, 0.f, 0.f);

    for (int kh = 0; kh < 2; kh++) {
        // load A chunk [128][64] and W chunk [128][64]
#pragma unroll
        for (int i = 0; i < 8; i++) {
            int e = t + i * 256;          // 0..2047
            int row = e >> 4, c4 = (e & 15) << 2;
            int gcol = kh * KCH + c4;
            float4 av = make_float4(0.f, 0.f, 0.f, 0.f);
            int m = m0 + row;
            if (m < M) av = __ldg((const float4*)(A + (size_t)m * HD + gcol));
            *(float4*)(As + row * SSTR + c4) = av;
            float4 wv = __ldg((const float4*)(W + (size_t)row * HD + gcol));
            *(float4*)(Ws + row * SSTR + c4) = wv;
        }
        __syncthreads();

#pragma unroll
        for (int ks = 0; ks < 8; ks++) {
            int kk = ks * 8;
            // B fragments for 4 n-tiles
            unsigned bh0[4], bl0[4], bh1[4], bl1[4];
#pragma unroll
            for (int nt = 0; nt < 4; nt++) {
                int n = wn * 32 + nt * 8 + g;
                float b0f = Ws[n * SSTR + kk + tg];
                float b1f = Ws[n * SSTR + kk + 4 + tg];
                split_tf32(b0f, bh0[nt], bl0[nt]);
                split_tf32(b1f, bh1[nt], bl1[nt]);
            }
#pragma unroll
            for (int mt = 0; mt < 4; mt++) {
                int r = wm * 64 + mt * 16 + g;
                int base = r * SSTR + kk + tg;
                float a0f = As[base];
                float a1f = As[base + 8 * SSTR];
                float a2f = As[base + 4];
                float a3f = As[base + 8 * SSTR + 4];
                unsigned ah0, al0, ah1, al1, ah2, al2, ah3, al3;
                split_tf32(a0f, ah0, al0);
                split_tf32(a1f, ah1, al1);
                split_tf32(a2f, ah2, al2);
                split_tf32(a3f, ah3, al3);
#pragma unroll
                for (int nt = 0; nt < 4; nt++) {
                    mma8(acc[mt][nt], ah0, ah1, ah2, ah3, bh0[nt], bh1[nt]);
                    mma8(acc[mt][nt], ah0, ah1, ah2, ah3, bl0[nt], bl1[nt]);
                    mma8(acc[mt][nt], al0, al1, al2, al3, bh0[nt], bh1[nt]);
                }
            }
        }
        __syncthreads();
    }

    // epilogue
#pragma unroll
    for (int mt = 0; mt < 4; mt++) {
        int r0 = m0 + wm * 64 + mt * 16 + g;
        int r1 = r0 + 8;
#pragma unroll
        for (int nt = 0; nt < 4; nt++) {
            int cb = wn * 32 + nt * 8 + tg * 2;
            float bv0 = __ldg(bias + cb), bv1 = __ldg(bias + cb + 1);
            if (r0 < M) {
                float2 o = make_float2(acc[mt][nt].x + bv0, acc[mt][nt].y + bv1);
                *(float2*)(C + (size_t)r0 * HD + cb) = o;
            }
            if (r1 < M) {
                float2 o = make_float2(acc[mt][nt].z + bv0, acc[mt][nt].w + bv1);
                *(float2*)(C + (size_t)r1 * HD + cb) = o;
            }
        }
    }
}

// ---------------- batchnorm ----------------
__global__ void k_colstats(const float* __restrict__ in, float* __restrict__ stat, int M) {
    int c = threadIdx.x;
    float s = 0.f, q = 0.f;
    for (int r = blockIdx.x; r < M; r += gridDim.x) {
        float v = in[(size_t)r * HD + c];
        s += v; q += v * v;
    }
    atomicAdd(&stat[c], s);
    atomicAdd(&stat[128 + c], q);
}

// finalize scale/shift per block, then stream normalize+relu
__global__ void k_bnrelu(const float* __restrict__ in, const float* __restrict__ stat,
                         const float* __restrict__ gamma, const float* __restrict__ beta,
                         float* __restrict__ out, int M) {
    __shared__ float sc[128], sh[128];
    if (threadIdx.x < 128) {
        int c = threadIdx.x;
        float mean = stat[c] / (float)M;
        float var = stat[128 + c] / (float)M - mean * mean;
        float s = gamma[c] * rsqrtf(var + 1e-5f);
        sc[c] = s;
        sh[c] = beta[c] - mean * s;
    }
    __syncthreads();
    int total = M * 32;
    for (int i = blockIdx.x * blockDim.x + threadIdx.x; i < total;
         i += gridDim.x * blockDim.x) {
        int c = (i & 31) * 4;
        float4 v = ((const float4*)in)[i];
        v.x = fmaxf(0.f, v.x * sc[c + 0] + sh[c + 0]);
        v.y = fmaxf(0.f, v.y * sc[c + 1] + sh[c + 1]);
        v.z = fmaxf(0.f, v.z * sc[c + 2] + sh[c + 2]);
        v.w = fmaxf(0.f, v.w * sc[c + 3] + sh[c + 3]);
        ((float4*)out)[i] = v;
    }
}

// ---------------- fused LSTM cell ----------------
__global__ void __launch_bounds__(256) k_lstm(const float* __restrict__ X, int D,
                                              const float* __restrict__ hprev,
                                              const float* __restrict__ Wih,
                                              const float* __restrict__ Whh,
                                              const float* __restrict__ bias,
                                              const float* __restrict__ cprev,
                                              float* __restrict__ hout,
                                              float* __restrict__ cout) {
    __shared__ float Xs[32][16];
    __shared__ float Ws[32][68];
    int m0 = blockIdx.x * 16, c0 = blockIdx.y * 16;
    int t = threadIdx.x, ty = t >> 4, tx = t & 15;
    float acc[4] = {0.f, 0.f, 0.f, 0.f};
    int total = D + 128;
    for (int k0 = 0; k0 < total; k0 += 32) {
        const float* src; int sstride, kb;
        const float* w; int wstride;
        if (k0 < D) { src = X; sstride = D; kb = k0; w = Wih; wstride = D; }
        else { src = hprev; sstride = 128; kb = k0 - D; w = Whh; wstride = 128; }
#pragma unroll
        for (int u = 0; u < 2; u++) {
            int e = t + u * 256;
            int kk = e >> 4, mm = e & 15;
            Xs[kk][mm] = __ldg(src + (size_t)(m0 + mm) * sstride + kb + kk);
        }
#pragma unroll
        for (int u = 0; u < 8; u++) {
            int e = t + u * 256;
            int kk = e >> 6, nn = e & 63;
            int gg = nn >> 4, ci = nn & 15;
            Ws[kk][nn] = __ldg(w + (size_t)(gg * 128 + c0 + ci) * wstride + kb + kk);
        }
        __syncthreads();
#pragma unroll 8
        for (int kk = 0; kk < 32; kk++) {
            float a = Xs[kk][ty];
            acc[0] += a * Ws[kk][tx];
            acc[1] += a * Ws[kk][16 + tx];
            acc[2] += a * Ws[kk][32 + tx];
            acc[3] += a * Ws[kk][48 + tx];
        }
        __syncthreads();
    }
    int b = m0 + ty, c = c0 + tx;
    float gi = acc[0] + __ldg(bias + c);
    float gf = acc[1] + __ldg(bias + 128 + c);
    float gc = acc[2] + __ldg(bias + 256 + c);
    float go = acc[3] + __ldg(bias + 384 + c);
    int idx = b * HD + c;
    float si = 1.f / (1.f + __expf(-gi));
    float sf = 1.f / (1.f + __expf(-gf));
    float so = 1.f / (1.f + __expf(-go));
    float cn = sf * cprev[idx] + si * tanhf(gc);
    cout[idx] = cn;
    hout[idx] = so * tanhf(cn);
}

// ---------------- attention ----------------
__global__ void k_attn_e(const float* __restrict__ xf, const float* __restrict__ q,
                         const int* __restrict__ batch, unsigned* __restrict__ marr) {
    int gw = (blockIdx.x * blockDim.x + threadIdx.x) >> 5;
    int lane = threadIdx.x & 31;
    int n0 = gw * 16;
    if (n0 >= NN) return;
    int n1 = min(n0 + 16, NN);
    const float4* x4 = (const float4*)xf;
    const float4* q4 = (const float4*)q;
    int runb = -1; float runmax = 0.f;
    for (int n = n0; n < n1; n++) {
        int b = __ldg(batch + n);
        float4 xv = x4[(size_t)n * 32 + lane];
        float4 qv = __ldg(&q4[(size_t)b * 32 + lane]);
        float d = xv.x * qv.x + xv.y * qv.y + xv.z * qv.z + xv.w * qv.w;
#pragma unroll
        for (int off = 16; off; off >>= 1) d += __shfl_xor_sync(0xffffffffu, d, off);
        if (lane == 0) g_e[n] = d;
        if (b != runb) {
            if (runb >= 0 && lane == 0) atomicMax(marr + runb, fenc(runmax));
            runb = b; runmax = d;
        } else runmax = fmaxf(runmax, d);
    }
    if (runb >= 0 && lane == 0) atomicMax(marr + runb, fenc(runmax));
}

__global__ void k_attn_r(const float* __restrict__ xf, const int* __restrict__ batch,
                         const unsigned* __restrict__ marr,
                         float* __restrict__ rnum, float* __restrict__ sarr) {
    int gw = (blockIdx.x * blockDim.x + threadIdx.x) >> 5;
    int lane = threadIdx.x & 31;
    int n0 = gw * 64;
    if (n0 >= NN) return;
    int n1 = min(n0 + 64, NN);
    const float4* x4 = (const float4*)xf;
    float4 acc = make_float4(0.f, 0.f, 0.f, 0.f);
    float se = 0.f;
    int runb = -1; float mb = 0.f;
    for (int n = n0; n < n1; n++) {
        int b = __ldg(batch + n);
        if (b != runb) {
            if (runb >= 0) {
                float* dst = rnum + (size_t)runb * HD + lane * 4;
                atomicAdd(dst + 0, acc.x); atomicAdd(dst + 1, acc.y);
                atomicAdd(dst + 2, acc.z); atomicAdd(dst + 3, acc.w);
                if (lane == 0) atomicAdd(sarr + runb, se);
                acc = make_float4(0.f, 0.f, 0.f, 0.f); se = 0.f;
            }
            runb = b;
            mb = fdec(__ldg(marr + b));
        }
        float ee = __expf(g_e[n] - mb);
        float4 xv = x4[(size_t)n * 32 + lane];
        acc.x += ee * xv.x; acc.y += ee * xv.y;
        acc.z += ee * xv.z; acc.w += ee * xv.w;
        se += ee;
    }
    if (runb >= 0) {
        float* dst = rnum + (size_t)runb * HD + lane * 4;
        atomicAdd(dst + 0, acc.x); atomicAdd(dst + 1, acc.y);
        atomicAdd(dst + 2, acc.z); atomicAdd(dst + 3, acc.w);
        if (lane == 0) atomicAdd(sarr + runb, se);
    }
}

__global__ void k_attn_fin(const float* __restrict__ q, const float* __restrict__ rnum,
                           const float* __restrict__ sarr, float* __restrict__ qstar) {
    int idx = blockIdx.x * blockDim.x + threadIdx.x;
    if (idx >= BGR * 2 * HD) return;
    int b = idx >> 8, c = idx & 255;
    float v;
    if (c < 128) v = q[b * HD + c];
    else {
        float s = sarr[b];
        v = (s > 0.f) ? rnum[b * HD + (c - 128)] / s : 0.f;
    }
    qstar[idx] = v;
}

// ---------------- final linear ----------------
__global__ void k_final(const float* __restrict__ qstar, const float* __restrict__ linW,
                        const float* __restrict__ linb, float* __restrict__ out) {
    int gw = (blockIdx.x * blockDim.x + threadIdx.x) >> 5;
    int lane = threadIdx.x & 31;
    if (gw >= BGR * 2) return;
    int b = gw >> 1, o = gw & 1;
    const float4* q4 = (const float4*)(qstar + b * 256);
    const float4* w4 = (const float4*)(linW + o * 256);
    float d = 0.f;
#pragma unroll
    for (int u = 0; u < 2; u++) {
        float4 a = q4[lane + u * 32];
        float4 w = __ldg(&w4[lane + u * 32]);
        d += a.x * w.x + a.y * w.y + a.z * w.z + a.w * w.w;
    }
#pragma unroll
    for (int off = 16; off; off >>= 1) d += __shfl_xor_sync(0xffffffffu, d, off);
    if (lane == 0) out[b * 2 + o] = d + __ldg(linb + o);
}

// ---------------- host ----------------
static float* symf(const void* sym) {
    void* p = nullptr;
    cudaGetSymbolAddress(&p, sym);
    return (float*)p;
}

extern "C" void kernel_launch(void* const* d_in, const int* in_sizes, int n_in,
                              void* d_out, int out_size) {
    const float* x     = (const float*)d_in[0];
    const int*   ei    = (const int*)d_in[1];
    const int*   batch = (const int*)d_in[2];
    const float* gW1[2] = {(const float*)d_in[3],  (const float*)d_in[11]};
    const float* gb1[2] = {(const float*)d_in[4],  (const float*)d_in[12]};
    const float* gg1[2] = {(const float*)d_in[5],  (const float*)d_in[13]};
    const float* ge1[2] = {(const float*)d_in[6],  (const float*)d_in[14]};
    const float* gW2[2] = {(const float*)d_in[7],  (const float*)d_in[15]};
    const float* gb2[2] = {(const float*)d_in[8],  (const float*)d_in[16]};
    const float* gg2[2] = {(const float*)d_in[9],  (const float*)d_in[17]};
    const float* ge2[2] = {(const float*)d_in[10], (const float*)d_in[18]};
    const float* Wih0 = (const float*)d_in[19];
    const float* Whh0 = (const float*)d_in[20];
    const float* b0   = (const float*)d_in[21];
    const float* WihR = (const float*)d_in[22];
    const float* WhhR = (const float*)d_in[23];
    const float* bR   = (const float*)d_in[24];
    const float* linW = (const float*)d_in[25];
    const float* linb = (const float*)d_in[26];
    float* out = (float*)d_out;

    float* agg   = symf(g_agg);
    float* tmp   = symf(g_tmp);
    float* feat  = symf(g_feat);
    float* stats = symf(g_stats);
    float* hbuf  = symf(g_h);
    float* cbuf  = symf(g_c);
    float* qstar = symf(g_qstar);
    void* pm = nullptr; cudaGetSymbolAddress(&pm, g_m);
    unsigned* marr = (unsigned*)pm;
    float* sarr  = symf(g_s);
    float* rnum  = symf(g_rnum);

    const int gemmSmem = 2 * 128 * SSTR * sizeof(float);   // 69632
    cudaFuncSetAttribute(k_gemm_tf32, cudaFuncAttributeMaxDynamicSharedMemorySize,
                         gemmSmem);

    k_zero<<<256, 256>>>();
    k_hist<<<(NE + 255) / 256, 256>>>(ei);
    k_scan<<<1, 1024>>>();
    k_scatter<<<(NE + 255) / 256, 256>>>(ei);

    int gemmBlocks = (NN + 127) / 128;
    int gatherBlocks = (NN * 32 + 255) / 256;

    const float* layerIn = x;
    for (int l = 0; l < 2; l++) {
        k_gather<<<gatherBlocks, 256>>>(layerIn, agg);
        float* st1 = stats + (l * 2 + 0) * 512;
        float* st2 = stats + (l * 2 + 1) * 512;
        k_gemm_tf32<<<gemmBlocks, 256, gemmSmem>>>(agg, gW1[l], gb1[l], tmp, NN);
        k_colstats<<<256, 128>>>(tmp, st1, NN);
        k_bnrelu<<<2048, 256>>>(tmp, st1, gg1[l], ge1[l], tmp, NN);
        k_gemm_tf32<<<gemmBlocks, 256, gemmSmem>>>(tmp, gW2[l], gb2[l], agg, NN);
        k_colstats<<<256, 128>>>(agg, st2, NN);
        k_bnrelu<<<2048, 256>>>(agg, st2, gg2[l], ge2[l], feat, NN);
        layerIn = feat;
    }

    dim3 lstmGrid(BGR / 16, HD / 16);
    int attnEBlocks = ((NN + 15) / 16 * 32 + 255) / 256;
    int attnRBlocks = ((NN + 63) / 64 * 32 + 255) / 256;

    for (int s = 0; s < 4; s++) {
        int p = s & 1;
        float* hOld = hbuf + p * 4 * BH;
        float* hNew = hbuf + (p ^ 1) * 4 * BH;
        float* cOld = cbuf + p * 4 * BH;
        float* cNew = cbuf + (p ^ 1) * 4 * BH;
        for (int l = 0; l < 4; l++) {
            const float* X = (l == 0) ? qstar : (hNew + (l - 1) * BH);
            int D = (l == 0) ? 256 : 128;
            const float* Wih = (l == 0) ? Wih0 : (WihR + (size_t)(l - 1) * 512 * 128);
            const float* Whh = (l == 0) ? Whh0 : (WhhR + (size_t)(l - 1) * 512 * 128);
            const float* bb  = (l == 0) ? b0   : (bR + (size_t)(l - 1) * 512);
            k_lstm<<<lstmGrid, 256>>>(X, D, hOld + l * BH, Wih, Whh, bb,
                                      cOld + l * BH, hNew + l * BH, cNew + l * BH);
        }
        const float* q = hNew + 3 * BH;
        k_attn_e<<<attnEBlocks, 256>>>(feat, q, batch, marr + s * BGR);
        k_attn_r<<<attnRBlocks, 256>>>(feat, batch, marr + s * BGR,
                                       rnum + s * BH, sarr + s * BGR);
        k_attn_fin<<<(BGR * 2 * HD + 255) / 256, 256>>>(q, rnum + s * BH,
                                                        sarr + s * BGR, qstar);
    }

    k_final<<<(BGR * 2 * 32 + 255) / 256, 256>>>(qstar, linW, linb, out);
}

// round 4
// speedup vs baseline: 1.3498x; 1.2359x over previous
#include <cuda_runtime.h>
#include <math.h>

#define NN 50000
#define NE 800000
#define BGR 256
#define HD 128
#define NHF (NN * HD)
#define BH (BGR * HD)
#define SCB 49   // ceil(NN/1024)

// ---------------- device scratch ----------------
__device__ __align__(16) float g_agg[NHF];
__device__ __align__(16) float g_tmp[NHF];
__device__ __align__(16) float g_feat[NHF];
__device__ int g_cnt[NN];
__device__ int g_rowstart[NN + 1];
__device__ int g_cursor[NN];
__device__ int g_eidsrc[NE];
__device__ int g_bsum[SCB];
__device__ int g_boff[SCB];
__device__ __align__(16) float g_stats[4 * 512];
__device__ __align__(16) float g_h[2 * 4 * BH];
__device__ __align__(16) float g_c[2 * 4 * BH];
__device__ __align__(16) float g_qstar[BGR * 2 * HD];
__device__ float g_e[NN];
__device__ unsigned g_m[4 * BGR];
__device__ float g_s[4 * BGR];
__device__ __align__(16) float g_rnum[4 * BH];

__device__ __forceinline__ unsigned fenc(float f) {
    int i = __float_as_int(f);
    return (i >= 0) ? ((unsigned)i | 0x80000000u) : (unsigned)(~i);
}
__device__ __forceinline__ float fdec(unsigned u) {
    return (u & 0x80000000u) ? __int_as_float((int)(u & 0x7fffffffu))
                             : __int_as_float(~(int)u);
}

// ---------------- init ----------------
__global__ void k_zero() {
    int i0 = blockIdx.x * blockDim.x + threadIdx.x;
    int st = gridDim.x * blockDim.x;
    for (int i = i0; i < NN; i += st) g_cnt[i] = 0;
    for (int i = i0; i < 4 * 512; i += st) g_stats[i] = 0.f;
    for (int i = i0; i < 2 * 4 * BH; i += st) { g_h[i] = 0.f; g_c[i] = 0.f; }
    for (int i = i0; i < 4 * BH; i += st) g_rnum[i] = 0.f;
    for (int i = i0; i < BGR * 2 * HD; i += st) g_qstar[i] = 0.f;
    for (int i = i0; i < 4 * BGR; i += st) { g_m[i] = 0u; g_s[i] = 0.f; }
}

// ---------------- CSR build ----------------
__global__ void k_hist(const int* __restrict__ ei) {
    int i = blockIdx.x * blockDim.x + threadIdx.x;
    if (i < NE) atomicAdd(&g_cnt[ei[NE + i]], 1);
}

// per-block exclusive scan, block totals to g_bsum
__global__ void k_scan1() {
    __shared__ int wsum[32];
    int tid = threadIdx.x, lane = tid & 31, wid = tid >> 5;
    int idx = blockIdx.x * 1024 + tid;
    int v = (idx < NN) ? g_cnt[idx] : 0;
    int incl = v;
#pragma unroll
    for (int off = 1; off < 32; off <<= 1) {
        int t = __shfl_up_sync(0xffffffffu, incl, off);
        if (lane >= off) incl += t;
    }
    if (lane == 31) wsum[wid] = incl;
    __syncthreads();
    if (wid == 0) {
        int wv = wsum[lane];
        int wincl = wv;
#pragma unroll
        for (int off = 1; off < 32; off <<= 1) {
            int t = __shfl_up_sync(0xffffffffu, wincl, off);
            if (lane >= off) wincl += t;
        }
        wsum[lane] = wincl - wv;
    }
    __syncthreads();
    int excl = wsum[wid] + incl - v;
    if (idx < NN) g_rowstart[idx] = excl;
    if (tid == 1023) g_bsum[blockIdx.x] = excl + v;
}

// scan the 49 block totals
__global__ void k_scan2() {
    __shared__ int sh[64];
    int t = threadIdx.x;  // 64 threads
    int v = (t < SCB) ? g_bsum[t] : 0;
    sh[t] = v;
    __syncthreads();
#pragma unroll
    for (int off = 1; off < 64; off <<= 1) {
        int add = (t >= off) ? sh[t - off] : 0;
        __syncthreads();
        sh[t] += add;
        __syncthreads();
    }
    if (t < SCB) g_boff[t] = sh[t] - v;
    if (t == SCB - 1) g_rowstart[NN] = sh[t];
}

// add block offsets, init cursor
__global__ void k_scan3() {
    int idx = blockIdx.x * blockDim.x + threadIdx.x;
    if (idx < NN) {
        int r = g_rowstart[idx] + g_boff[idx >> 10];
        g_rowstart[idx] = r;
        g_cursor[idx] = r;
    }
}

__global__ void k_scatter(const int* __restrict__ ei) {
    int i = blockIdx.x * blockDim.x + threadIdx.x;
    if (i < NE) {
        int pos = atomicAdd(&g_cursor[ei[NE + i]], 1);
        g_eidsrc[pos] = ei[i];
    }
}

// out[n] = x[n] + sum_{j->n} x[j]
__global__ void k_gather(const float* __restrict__ xin, float* __restrict__ out) {
    int gw = (blockIdx.x * blockDim.x + threadIdx.x) >> 5;
    int lane = threadIdx.x & 31;
    if (gw >= NN) return;
    const float4* x4 = (const float4*)xin;
    float4 acc = x4[(size_t)gw * 32 + lane];
    int s0 = g_rowstart[gw], s1 = g_rowstart[gw + 1];
    int j = s0;
    for (; j + 4 <= s1; j += 4) {
        int i0 = g_eidsrc[j], i1 = g_eidsrc[j + 1];
        int i2 = g_eidsrc[j + 2], i3 = g_eidsrc[j + 3];
        float4 v0 = __ldg(&x4[(size_t)i0 * 32 + lane]);
        float4 v1 = __ldg(&x4[(size_t)i1 * 32 + lane]);
        float4 v2 = __ldg(&x4[(size_t)i2 * 32 + lane]);
        float4 v3 = __ldg(&x4[(size_t)i3 * 32 + lane]);
        acc.x += (v0.x + v1.x) + (v2.x + v3.x);
        acc.y += (v0.y + v1.y) + (v2.y + v3.y);
        acc.z += (v0.z + v1.z) + (v2.z + v3.z);
        acc.w += (v0.w + v1.w) + (v2.w + v3.w);
    }
    for (; j < s1; j++) {
        float4 v = __ldg(&x4[(size_t)g_eidsrc[j] * 32 + lane]);
        acc.x += v.x; acc.y += v.y; acc.z += v.z; acc.w += v.w;
    }
    ((float4*)out)[(size_t)gw * 32 + lane] = acc;
}

// ---------------- tf32 helpers ----------------
__device__ __forceinline__ void split_tf32(float f, float& hi, float& lo) {
    unsigned h;
    asm("cvt.rna.tf32.f32 %0, %1;" : "=r"(h) : "f"(f));
    float r = f - __uint_as_float(h);
    unsigned l;
    asm("cvt.rna.tf32.f32 %0, %1;" : "=r"(l) : "f"(r));
    hi = __uint_as_float(h); lo = __uint_as_float(l);
}

__device__ __forceinline__ void mma8(float4& d, unsigned a0, unsigned a1,
                                     unsigned a2, unsigned a3,
                                     unsigned b0, unsigned b1) {
    asm volatile(
        "mma.sync.aligned.m16n8k8.row.col.f32.tf32.tf32.f32 "
        "{%0,%1,%2,%3},{%4,%5,%6,%7},{%8,%9},{%0,%1,%2,%3};\n"
        : "+f"(d.x), "+f"(d.y), "+f"(d.z), "+f"(d.w)
        : "r"(a0), "r"(a1), "r"(a2), "r"(a3), "r"(b0), "r"(b1));
}

// ---------------- GEMM: C = A @ W^T + b, fused column stats ----------------
// 128x128 block, 256 threads, warps 2(M) x 4(N), warp tile 64x32.
// tf32 hi/lo pre-split into smem planes at load; inner loop pure LDS+MMA.
#define KC 32
#define SST 36
__global__ void __launch_bounds__(256) k_gemm_tf32(const float* __restrict__ A,
                                                   const float* __restrict__ W,
                                                   const float* __restrict__ bias,
                                                   float* __restrict__ C,
                                                   float* __restrict__ stat, int M) {
    extern __shared__ float sm[];
    float* Ah = sm;
    float* Al = Ah + 128 * SST;
    float* Wh = Al + 128 * SST;
    float* Wl = Wh + 128 * SST;
    int m0 = blockIdx.x * 128;
    int t = threadIdx.x, wid = t >> 5, lane = t & 31;
    int wm = wid >> 2, wn = wid & 3;
    int g = lane >> 2, tg = lane & 3;

    float4 acc[4][4];
#pragma unroll
    for (int i = 0; i < 4; i++)
#pragma unroll
        for (int j = 0; j < 4; j++) acc[i][j] = make_float4(0.f, 0.f, 0.f, 0.f);

    for (int kc = 0; kc < 4; kc++) {
#pragma unroll
        for (int u = 0; u < 4; u++) {
            int e = t + u * 256;          // 0..1023 float4 slots
            int row = e >> 3;
            int c4 = (e & 7) << 2;
            int gcol = kc * KC + c4;
            float4 av = make_float4(0.f, 0.f, 0.f, 0.f);
            if (m0 + row < M) av = __ldg((const float4*)(A + (size_t)(m0 + row) * HD + gcol));
            float4 wv = __ldg((const float4*)(W + (size_t)row * HD + gcol));
            float h0, l0, h1, l1, h2, l2, h3, l3;
            split_tf32(av.x, h0, l0); split_tf32(av.y, h1, l1);
            split_tf32(av.z, h2, l2); split_tf32(av.w, h3, l3);
            int b = row * SST + c4;
            *(float4*)(Ah + b) = make_float4(h0, h1, h2, h3);
            *(float4*)(Al + b) = make_float4(l0, l1, l2, l3);
            split_tf32(wv.x, h0, l0); split_tf32(wv.y, h1, l1);
            split_tf32(wv.z, h2, l2); split_tf32(wv.w, h3, l3);
            *(float4*)(Wh + b) = make_float4(h0, h1, h2, h3);
            *(float4*)(Wl + b) = make_float4(l0, l1, l2, l3);
        }
        __syncthreads();

#pragma unroll
        for (int ks = 0; ks < 4; ks++) {
            int kk = ks * 8;
            unsigned bh0[4], bh1[4], bl0[4], bl1[4];
#pragma unroll
            for (int nt = 0; nt < 4; nt++) {
                int nb = (wn * 32 + nt * 8 + g) * SST + kk + tg;
                bh0[nt] = __float_as_uint(Wh[nb]);
                bh1[nt] = __float_as_uint(Wh[nb + 4]);
                bl0[nt] = __float_as_uint(Wl[nb]);
                bl1[nt] = __float_as_uint(Wl[nb + 4]);
            }
#pragma unroll
            for (int mt = 0; mt < 4; mt++) {
                int base = (wm * 64 + mt * 16 + g) * SST + kk + tg;
                unsigned ah0 = __float_as_uint(Ah[base]);
                unsigned ah1 = __float_as_uint(Ah[base + 8 * SST]);
                unsigned ah2 = __float_as_uint(Ah[base + 4]);
                unsigned ah3 = __float_as_uint(Ah[base + 8 * SST + 4]);
                unsigned al0 = __float_as_uint(Al[base]);
                unsigned al1 = __float_as_uint(Al[base + 8 * SST]);
                unsigned al2 = __float_as_uint(Al[base + 4]);
                unsigned al3 = __float_as_uint(Al[base + 8 * SST + 4]);
#pragma unroll
                for (int nt = 0; nt < 4; nt++) {
                    mma8(acc[mt][nt], ah0, ah1, ah2, ah3, bh0[nt], bh1[nt]);
                    mma8(acc[mt][nt], ah0, ah1, ah2, ah3, bl0[nt], bl1[nt]);
                    mma8(acc[mt][nt], al0, al1, al2, al3, bh0[nt], bh1[nt]);
                }
            }
        }
        __syncthreads();
    }

    // epilogue: bias add, store, fused column sum/sumsq
#pragma unroll
    for (int nt = 0; nt < 4; nt++) {
        int cb = wn * 32 + nt * 8 + tg * 2;
        float bv0 = __ldg(bias + cb), bv1 = __ldg(bias + cb + 1);
        float sA = 0.f, sB = 0.f, qA = 0.f, qB = 0.f;
#pragma unroll
        for (int mt = 0; mt < 4; mt++) {
            int r0 = m0 + wm * 64 + mt * 16 + g;
            int r1 = r0 + 8;
            if (r0 < M) {
                float v0 = acc[mt][nt].x + bv0, v1 = acc[mt][nt].y + bv1;
                *(float2*)(C + (size_t)r0 * HD + cb) = make_float2(v0, v1);
                sA += v0; qA += v0 * v0; sB += v1; qB += v1 * v1;
            }
            if (r1 < M) {
                float v2 = acc[mt][nt].z + bv0, v3 = acc[mt][nt].w + bv1;
                *(float2*)(C + (size_t)r1 * HD + cb) = make_float2(v2, v3);
                sA += v2; qA += v2 * v2; sB += v3; qB += v3 * v3;
            }
        }
#pragma unroll
        for (int off = 4; off <= 16; off <<= 1) {
            sA += __shfl_xor_sync(0xffffffffu, sA, off);
            sB += __shfl_xor_sync(0xffffffffu, sB, off);
            qA += __shfl_xor_sync(0xffffffffu, qA, off);
            qB += __shfl_xor_sync(0xffffffffu, qB, off);
        }
        if (g == 0) {
            atomicAdd(stat + cb, sA);
            atomicAdd(stat + cb + 1, sB);
            atomicAdd(stat + 128 + cb, qA);
            atomicAdd(stat + 128 + cb + 1, qB);
        }
    }
}

// ---------------- batchnorm apply ----------------
__global__ void k_bnrelu(const float* __restrict__ in, const float* __restrict__ stat,
                         const float* __restrict__ gamma, const float* __restrict__ beta,
                         float* __restrict__ out, int M) {
    __shared__ float sc[128], sh[128];
    if (threadIdx.x < 128) {
        int c = threadIdx.x;
        float mean = stat[c] / (float)M;
        float var = stat[128 + c] / (float)M - mean * mean;
        float s = gamma[c] * rsqrtf(var + 1e-5f);
        sc[c] = s;
        sh[c] = beta[c] - mean * s;
    }
    __syncthreads();
    int total = M * 32;
    for (int i = blockIdx.x * blockDim.x + threadIdx.x; i < total;
         i += gridDim.x * blockDim.x) {
        int c = (i & 31) * 4;
        float4 v = ((const float4*)in)[i];
        v.x = fmaxf(0.f, v.x * sc[c + 0] + sh[c + 0]);
        v.y = fmaxf(0.f, v.y * sc[c + 1] + sh[c + 1]);
        v.z = fmaxf(0.f, v.z * sc[c + 2] + sh[c + 2]);
        v.w = fmaxf(0.f, v.w * sc[c + 3] + sh[c + 3]);
        ((float4*)out)[i] = v;
    }
}

// ---------------- fused LSTM cell ----------------
__global__ void __launch_bounds__(256) k_lstm(const float* __restrict__ X, int D,
                                              const float* __restrict__ hprev,
                                              const float* __restrict__ Wih,
                                              const float* __restrict__ Whh,
                                              const float* __restrict__ bias,
                                              const float* __restrict__ cprev,
                                              float* __restrict__ hout,
                                              float* __restrict__ cout) {
    __shared__ float Xs[32][16];
    __shared__ float Ws[32][68];
    int m0 = blockIdx.x * 16, c0 = blockIdx.y * 16;
    int t = threadIdx.x, ty = t >> 4, tx = t & 15;
    float acc[4] = {0.f, 0.f, 0.f, 0.f};
    int total = D + 128;
    for (int k0 = 0; k0 < total; k0 += 32) {
        const float* src; int sstride, kb;
        const float* w; int wstride;
        if (k0 < D) { src = X; sstride = D; kb = k0; w = Wih; wstride = D; }
        else { src = hprev; sstride = 128; kb = k0 - D; w = Whh; wstride = 128; }
#pragma unroll
        for (int u = 0; u < 2; u++) {
            int e = t + u * 256;
            int kk = e >> 4, mm = e & 15;
            Xs[kk][mm] = __ldg(src + (size_t)(m0 + mm) * sstride + kb + kk);
        }
#pragma unroll
        for (int u = 0; u < 8; u++) {
            int e = t + u * 256;
            int kk = e >> 6, nn = e & 63;
            int gg = nn >> 4, ci = nn & 15;
            Ws[kk][nn] = __ldg(w + (size_t)(gg * 128 + c0 + ci) * wstride + kb + kk);
        }
        __syncthreads();
#pragma unroll 8
        for (int kk = 0; kk < 32; kk++) {
            float a = Xs[kk][ty];
            acc[0] += a * Ws[kk][tx];
            acc[1] += a * Ws[kk][16 + tx];
            acc[2] += a * Ws[kk][32 + tx];
            acc[3] += a * Ws[kk][48 + tx];
        }
        __syncthreads();
    }
    int b = m0 + ty, c = c0 + tx;
    float gi = acc[0] + __ldg(bias + c);
    float gf = acc[1] + __ldg(bias + 128 + c);
    float gc = acc[2] + __ldg(bias + 256 + c);
    float go = acc[3] + __ldg(bias + 384 + c);
    int idx = b * HD + c;
    float si = 1.f / (1.f + __expf(-gi));
    float sf = 1.f / (1.f + __expf(-gf));
    float so = 1.f / (1.f + __expf(-go));
    float cn = sf * cprev[idx] + si * tanhf(gc);
    cout[idx] = cn;
    hout[idx] = so * tanhf(cn);
}

// ---------------- attention ----------------
__global__ void k_attn_e(const float* __restrict__ xf, const float* __restrict__ q,
                         const int* __restrict__ batch, unsigned* __restrict__ marr) {
    int gw = (blockIdx.x * blockDim.x + threadIdx.x) >> 5;
    int lane = threadIdx.x & 31;
    int n0 = gw * 16;
    if (n0 >= NN) return;
    int n1 = min(n0 + 16, NN);
    const float4* x4 = (const float4*)xf;
    const float4* q4 = (const float4*)q;
    int runb = -1; float runmax = 0.f;
    for (int n = n0; n < n1; n++) {
        int b = __ldg(batch + n);
        float4 xv = x4[(size_t)n * 32 + lane];
        float4 qv = __ldg(&q4[(size_t)b * 32 + lane]);
        float d = xv.x * qv.x + xv.y * qv.y + xv.z * qv.z + xv.w * qv.w;
#pragma unroll
        for (int off = 16; off; off >>= 1) d += __shfl_xor_sync(0xffffffffu, d, off);
        if (lane == 0) g_e[n] = d;
        if (b != runb) {
            if (runb >= 0 && lane == 0) atomicMax(marr + runb, fenc(runmax));
            runb = b; runmax = d;
        } else runmax = fmaxf(runmax, d);
    }
    if (runb >= 0 && lane == 0) atomicMax(marr + runb, fenc(runmax));
}

__global__ void k_attn_r(const float* __restrict__ xf, const int* __restrict__ batch,
                         const unsigned* __restrict__ marr,
                         float* __restrict__ rnum, float* __restrict__ sarr) {
    int gw = (blockIdx.x * blockDim.x + threadIdx.x) >> 5;
    int lane = threadIdx.x & 31;
    int n0 = gw * 64;
    if (n0 >= NN) return;
    int n1 = min(n0 + 64, NN);
    const float4* x4 = (const float4*)xf;
    float4 acc = make_float4(0.f, 0.f, 0.f, 0.f);
    float se = 0.f;
    int runb = -1; float mb = 0.f;
    for (int n = n0; n < n1; n++) {
        int b = __ldg(batch + n);
        if (b != runb) {
            if (runb >= 0) {
                float* dst = rnum + (size_t)runb * HD + lane * 4;
                atomicAdd(dst + 0, acc.x); atomicAdd(dst + 1, acc.y);
                atomicAdd(dst + 2, acc.z); atomicAdd(dst + 3, acc.w);
                if (lane == 0) atomicAdd(sarr + runb, se);
                acc = make_float4(0.f, 0.f, 0.f, 0.f); se = 0.f;
            }
            runb = b;
            mb = fdec(__ldg(marr + b));
        }
        float ee = __expf(g_e[n] - mb);
        float4 xv = x4[(size_t)n * 32 + lane];
        acc.x += ee * xv.x; acc.y += ee * xv.y;
        acc.z += ee * xv.z; acc.w += ee * xv.w;
        se += ee;
    }
    if (runb >= 0) {
        float* dst = rnum + (size_t)runb * HD + lane * 4;
        atomicAdd(dst + 0, acc.x); atomicAdd(dst + 1, acc.y);
        atomicAdd(dst + 2, acc.z); atomicAdd(dst + 3, acc.w);
        if (lane == 0) atomicAdd(sarr + runb, se);
    }
}

__global__ void k_attn_fin(const float* __restrict__ q, const float* __restrict__ rnum,
                           const float* __restrict__ sarr, float* __restrict__ qstar) {
    int idx = blockIdx.x * blockDim.x + threadIdx.x;
    if (idx >= BGR * 2 * HD) return;
    int b = idx >> 8, c = idx & 255;
    float v;
    if (c < 128) v = q[b * HD + c];
    else {
        float s = sarr[b];
        v = (s > 0.f) ? rnum[b * HD + (c - 128)] / s : 0.f;
    }
    qstar[idx] = v;
}

// ---------------- final linear ----------------
__global__ void k_final(const float* __restrict__ qstar, const float* __restrict__ linW,
                        const float* __restrict__ linb, float* __restrict__ out) {
    int gw = (blockIdx.x * blockDim.x + threadIdx.x) >> 5;
    int lane = threadIdx.x & 31;
    if (gw >= BGR * 2) return;
    int b = gw >> 1, o = gw & 1;
    const float4* q4 = (const float4*)(qstar + b * 256);
    const float4* w4 = (const float4*)(linW + o * 256);
    float d = 0.f;
#pragma unroll
    for (int u = 0; u < 2; u++) {
        float4 a = q4[lane + u * 32];
        float4 w = __ldg(&w4[lane + u * 32]);
        d += a.x * w.x + a.y * w.y + a.z * w.z + a.w * w.w;
    }
#pragma unroll
    for (int off = 16; off; off >>= 1) d += __shfl_xor_sync(0xffffffffu, d, off);
    if (lane == 0) out[b * 2 + o] = d + __ldg(linb + o);
}

// ---------------- host ----------------
static float* symf(const void* sym) {
    void* p = nullptr;
    cudaGetSymbolAddress(&p, sym);
    return (float*)p;
}

extern "C" void kernel_launch(void* const* d_in, const int* in_sizes, int n_in,
                              void* d_out, int out_size) {
    const float* x     = (const float*)d_in[0];
    const int*   ei    = (const int*)d_in[1];
    const int*   batch = (const int*)d_in[2];
    const float* gW1[2] = {(const float*)d_in[3],  (const float*)d_in[11]};
    const float* gb1[2] = {(const float*)d_in[4],  (const float*)d_in[12]};
    const float* gg1[2] = {(const float*)d_in[5],  (const float*)d_in[13]};
    const float* ge1[2] = {(const float*)d_in[6],  (const float*)d_in[14]};
    const float* gW2[2] = {(const float*)d_in[7],  (const float*)d_in[15]};
    const float* gb2[2] = {(const float*)d_in[8],  (const float*)d_in[16]};
    const float* gg2[2] = {(const float*)d_in[9],  (const float*)d_in[17]};
    const float* ge2[2] = {(const float*)d_in[10], (const float*)d_in[18]};
    const float* Wih0 = (const float*)d_in[19];
    const float* Whh0 = (const float*)d_in[20];
    const float* b0   = (const float*)d_in[21];
    const float* WihR = (const float*)d_in[22];
    const float* WhhR = (const float*)d_in[23];
    const float* bR   = (const float*)d_in[24];
    const float* linW = (const float*)d_in[25];
    const float* linb = (const float*)d_in[26];
    float* out = (float*)d_out;

    float* agg   = symf(g_agg);
    float* tmp   = symf(g_tmp);
    float* feat  = symf(g_feat);
    float* stats = symf(g_stats);
    float* hbuf  = symf(g_h);
    float* cbuf  = symf(g_c);
    float* qstar = symf(g_qstar);
    void* pm = nullptr; cudaGetSymbolAddress(&pm, g_m);
    unsigned* marr = (unsigned*)pm;
    float* sarr  = symf(g_s);
    float* rnum  = symf(g_rnum);

    const int gemmSmem = 4 * 128 * SST * sizeof(float);   // 73728
    cudaFuncSetAttribute(k_gemm_tf32, cudaFuncAttributeMaxDynamicSharedMemorySize,
                         gemmSmem);

    k_zero<<<256, 256>>>();
    k_hist<<<(NE + 255) / 256, 256>>>(ei);
    k_scan1<<<SCB, 1024>>>();
    k_scan2<<<1, 64>>>();
    k_scan3<<<(NN + 255) / 256, 256>>>();
    k_scatter<<<(NE + 255) / 256, 256>>>(ei);

    int gemmBlocks = (NN + 127) / 128;
    int gatherBlocks = (NN * 32 + 255) / 256;

    const float* layerIn = x;
    for (int l = 0; l < 2; l++) {
        k_gather<<<gatherBlocks, 256>>>(layerIn, agg);
        float* st1 = stats + (l * 2 + 0) * 512;
        float* st2 = stats + (l * 2 + 1) * 512;
        k_gemm_tf32<<<gemmBlocks, 256, gemmSmem>>>(agg, gW1[l], gb1[l], tmp, st1, NN);
        k_bnrelu<<<2048, 256>>>(tmp, st1, gg1[l], ge1[l], tmp, NN);
        k_gemm_tf32<<<gemmBlocks, 256, gemmSmem>>>(tmp, gW2[l], gb2[l], agg, st2, NN);
        k_bnrelu<<<2048, 256>>>(agg, st2, gg2[l], ge2[l], feat, NN);
        layerIn = feat;
    }

    dim3 lstmGrid(BGR / 16, HD / 16);
    int attnEBlocks = ((NN + 15) / 16 * 32 + 255) / 256;
    int attnRBlocks = ((NN + 63) / 64 * 32 + 255) / 256;

    for (int s = 0; s < 4; s++) {
        int p = s & 1;
        float* hOld = hbuf + p * 4 * BH;
        float* hNew = hbuf + (p ^ 1) * 4 * BH;
        float* cOld = cbuf + p * 4 * BH;
        float* cNew = cbuf + (p ^ 1) * 4 * BH;
        for (int l = 0; l < 4; l++) {
            const float* X = (l == 0) ? qstar : (hNew + (l - 1) * BH);
            int D = (l == 0) ? 256 : 128;
            const float* Wih = (l == 0) ? Wih0 : (WihR + (size_t)(l - 1) * 512 * 128);
            const float* Whh = (l == 0) ? Whh0 : (WhhR + (size_t)(l - 1) * 512 * 128);
            const float* bb  = (l == 0) ? b0   : (bR + (size_t)(l - 1) * 512);
            k_lstm<<<lstmGrid, 256>>>(X, D, hOld + l * BH, Wih, Whh, bb,
                                      cOld + l * BH, hNew + l * BH, cNew + l * BH);
        }
        const float* q = hNew + 3 * BH;
        k_attn_e<<<attnEBlocks, 256>>>(feat, q, batch, marr + s * BGR);
        k_attn_r<<<attnRBlocks, 256>>>(feat, batch, marr + s * BGR,
                                       rnum + s * BH, sarr + s * BGR);
        k_attn_fin<<<(BGR * 2 * HD + 255) / 256, 256>>>(q, rnum + s * BH,
                                                        sarr + s * BGR, qstar);
    }

    k_final<<<(BGR * 2 * 32 + 255) / 256, 256>>>(qstar, linW, linb, out);
}

// round 5
// speedup vs baseline: 1.4597x; 1.0814x over previous
#include <cuda_runtime.h>
#include <math.h>

#define NN 50000
#define NE 800000
#define BGR 256
#define HD 128
#define NHF (NN * HD)
#define BH (BGR * HD)
#define SCB 49   // ceil(NN/1024)
#define SECAP 2048

// ---------------- device scratch ----------------
__device__ __align__(16) float g_agg[NHF];
__device__ __align__(16) float g_tmp[NHF];
__device__ __align__(16) float g_feat[NHF];
__device__ int g_cnt[NN];
__device__ int g_rowstart[NN + 1];
__device__ int g_cursor[NN];
__device__ int g_eidsrc[NE];
__device__ int g_bsum[SCB];
__device__ int g_boff[SCB];
__device__ int g_goff[BGR + 1];
__device__ __align__(16) float g_stats[4 * 512];
__device__ __align__(16) float g_h[2 * 4 * BH];
__device__ __align__(16) float g_c[2 * 4 * BH];
__device__ __align__(16) float g_qstar[BGR * 2 * HD];

// ---------------- init ----------------
__global__ void k_zero() {
    int i0 = blockIdx.x * blockDim.x + threadIdx.x;
    int st = gridDim.x * blockDim.x;
    for (int i = i0; i < NN; i += st) g_cnt[i] = 0;
    for (int i = i0; i < 4 * 512; i += st) g_stats[i] = 0.f;
    for (int i = i0; i < 2 * 4 * BH; i += st) { g_h[i] = 0.f; g_c[i] = 0.f; }
    for (int i = i0; i < BGR * 2 * HD; i += st) g_qstar[i] = 0.f;
}

// ---------------- CSR build ----------------
__global__ void k_hist(const int* __restrict__ ei) {
    int i = blockIdx.x * blockDim.x + threadIdx.x;
    if (i < NE) atomicAdd(&g_cnt[ei[NE + i]], 1);
}

__global__ void k_scan1() {
    __shared__ int wsum[32];
    int tid = threadIdx.x, lane = tid & 31, wid = tid >> 5;
    int idx = blockIdx.x * 1024 + tid;
    int v = (idx < NN) ? g_cnt[idx] : 0;
    int incl = v;
#pragma unroll
    for (int off = 1; off < 32; off <<= 1) {
        int t = __shfl_up_sync(0xffffffffu, incl, off);
        if (lane >= off) incl += t;
    }
    if (lane == 31) wsum[wid] = incl;
    __syncthreads();
    if (wid == 0) {
        int wv = wsum[lane];
        int wincl = wv;
#pragma unroll
        for (int off = 1; off < 32; off <<= 1) {
            int t = __shfl_up_sync(0xffffffffu, wincl, off);
            if (lane >= off) wincl += t;
        }
        wsum[lane] = wincl - wv;
    }
    __syncthreads();
    int excl = wsum[wid] + incl - v;
    if (idx < NN) g_rowstart[idx] = excl;
    if (tid == 1023) g_bsum[blockIdx.x] = excl + v;
}

__global__ void k_scan2() {
    __shared__ int sh[64];
    int t = threadIdx.x;
    int v = (t < SCB) ? g_bsum[t] : 0;
    sh[t] = v;
    __syncthreads();
#pragma unroll
    for (int off = 1; off < 64; off <<= 1) {
        int add = (t >= off) ? sh[t - off] : 0;
        __syncthreads();
        sh[t] += add;
        __syncthreads();
    }
    if (t < SCB) g_boff[t] = sh[t] - v;
    if (t == SCB - 1) g_rowstart[NN] = sh[t];
}

__global__ void k_scan3() {
    int idx = blockIdx.x * blockDim.x + threadIdx.x;
    if (idx < NN) {
        int r = g_rowstart[idx] + g_boff[idx >> 10];
        g_rowstart[idx] = r;
        g_cursor[idx] = r;
    }
}

__global__ void k_scatter(const int* __restrict__ ei) {
    int i = blockIdx.x * blockDim.x + threadIdx.x;
    if (i < NE) {
        int pos = atomicAdd(&g_cursor[ei[NE + i]], 1);
        g_eidsrc[pos] = ei[i];
    }
}

// graph boundary offsets from sorted batch
__global__ void k_goff(const int* __restrict__ batch) {
    int n = blockIdx.x * blockDim.x + threadIdx.x;
    if (n >= NN) return;
    int bn = batch[n];
    int bp = (n == 0) ? -1 : batch[n - 1];
    for (int bb = bp + 1; bb <= bn; bb++) g_goff[bb] = n;
    if (n == NN - 1)
        for (int bb = bn + 1; bb <= BGR; bb++) g_goff[bb] = NN;
}

// out[n] = x[n] + sum_{j->n} x[j]
__global__ void k_gather(const float* __restrict__ xin, float* __restrict__ out) {
    int gw = (blockIdx.x * blockDim.x + threadIdx.x) >> 5;
    int lane = threadIdx.x & 31;
    if (gw >= NN) return;
    const float4* x4 = (const float4*)xin;
    float4 acc = x4[(size_t)gw * 32 + lane];
    int s0 = g_rowstart[gw], s1 = g_rowstart[gw + 1];
    int j = s0;
    for (; j + 4 <= s1; j += 4) {
        int i0 = g_eidsrc[j], i1 = g_eidsrc[j + 1];
        int i2 = g_eidsrc[j + 2], i3 = g_eidsrc[j + 3];
        float4 v0 = __ldg(&x4[(size_t)i0 * 32 + lane]);
        float4 v1 = __ldg(&x4[(size_t)i1 * 32 + lane]);
        float4 v2 = __ldg(&x4[(size_t)i2 * 32 + lane]);
        float4 v3 = __ldg(&x4[(size_t)i3 * 32 + lane]);
        acc.x += (v0.x + v1.x) + (v2.x + v3.x);
        acc.y += (v0.y + v1.y) + (v2.y + v3.y);
        acc.z += (v0.z + v1.z) + (v2.z + v3.z);
        acc.w += (v0.w + v1.w) + (v2.w + v3.w);
    }
    for (; j < s1; j++) {
        float4 v = __ldg(&x4[(size_t)g_eidsrc[j] * 32 + lane]);
        acc.x += v.x; acc.y += v.y; acc.z += v.z; acc.w += v.w;
    }
    ((float4*)out)[(size_t)gw * 32 + lane] = acc;
}

// ---------------- tf32 helpers ----------------
__device__ __forceinline__ void split_tf32(float f, float& hi, float& lo) {
    unsigned h;
    asm("cvt.rna.tf32.f32 %0, %1;" : "=r"(h) : "f"(f));
    float r = f - __uint_as_float(h);
    unsigned l;
    asm("cvt.rna.tf32.f32 %0, %1;" : "=r"(l) : "f"(r));
    hi = __uint_as_float(h); lo = __uint_as_float(l);
}

__device__ __forceinline__ void mma8(float4& d, unsigned a0, unsigned a1,
                                     unsigned a2, unsigned a3,
                                     unsigned b0, unsigned b1) {
    asm volatile(
        "mma.sync.aligned.m16n8k8.row.col.f32.tf32.tf32.f32 "
        "{%0,%1,%2,%3},{%4,%5,%6,%7},{%8,%9},{%0,%1,%2,%3};\n"
        : "+f"(d.x), "+f"(d.y), "+f"(d.z), "+f"(d.w)
        : "r"(a0), "r"(a1), "r"(a2), "r"(a3), "r"(b0), "r"(b1));
}

// ---------------- GEMM: C = A @ W^T + b, fused column stats ----------------
#define KC 32
#define SST 36
__global__ void __launch_bounds__(256) k_gemm_tf32(const float* __restrict__ A,
                                                   const float* __restrict__ W,
                                                   const float* __restrict__ bias,
                                                   float* __restrict__ C,
                                                   float* __restrict__ stat, int M) {
    extern __shared__ float sm[];
    float* Ah = sm;
    float* Al = Ah + 128 * SST;
    float* Wh = Al + 128 * SST;
    float* Wl = Wh + 128 * SST;
    int m0 = blockIdx.x * 128;
    int t = threadIdx.x, wid = t >> 5, lane = t & 31;
    int wm = wid >> 2, wn = wid & 3;
    int g = lane >> 2, tg = lane & 3;

    float4 acc[4][4];
#pragma unroll
    for (int i = 0; i < 4; i++)
#pragma unroll
        for (int j = 0; j < 4; j++) acc[i][j] = make_float4(0.f, 0.f, 0.f, 0.f);

    for (int kc = 0; kc < 4; kc++) {
#pragma unroll
        for (int u = 0; u < 4; u++) {
            int e = t + u * 256;
            int row = e >> 3;
            int c4 = (e & 7) << 2;
            int gcol = kc * KC + c4;
            float4 av = make_float4(0.f, 0.f, 0.f, 0.f);
            if (m0 + row < M) av = __ldg((const float4*)(A + (size_t)(m0 + row) * HD + gcol));
            float4 wv = __ldg((const float4*)(W + (size_t)row * HD + gcol));
            float h0, l0, h1, l1, h2, l2, h3, l3;
            split_tf32(av.x, h0, l0); split_tf32(av.y, h1, l1);
            split_tf32(av.z, h2, l2); split_tf32(av.w, h3, l3);
            int b = row * SST + c4;
            *(float4*)(Ah + b) = make_float4(h0, h1, h2, h3);
            *(float4*)(Al + b) = make_float4(l0, l1, l2, l3);
            split_tf32(wv.x, h0, l0); split_tf32(wv.y, h1, l1);
            split_tf32(wv.z, h2, l2); split_tf32(wv.w, h3, l3);
            *(float4*)(Wh + b) = make_float4(h0, h1, h2, h3);
            *(float4*)(Wl + b) = make_float4(l0, l1, l2, l3);
        }
        __syncthreads();

#pragma unroll
        for (int ks = 0; ks < 4; ks++) {
            int kk = ks * 8;
            unsigned bh0[4], bh1[4], bl0[4], bl1[4];
#pragma unroll
            for (int nt = 0; nt < 4; nt++) {
                int nb = (wn * 32 + nt * 8 + g) * SST + kk + tg;
                bh0[nt] = __float_as_uint(Wh[nb]);
                bh1[nt] = __float_as_uint(Wh[nb + 4]);
                bl0[nt] = __float_as_uint(Wl[nb]);
                bl1[nt] = __float_as_uint(Wl[nb + 4]);
            }
#pragma unroll
            for (int mt = 0; mt < 4; mt++) {
                int base = (wm * 64 + mt * 16 + g) * SST + kk + tg;
                unsigned ah0 = __float_as_uint(Ah[base]);
                unsigned ah1 = __float_as_uint(Ah[base + 8 * SST]);
                unsigned ah2 = __float_as_uint(Ah[base + 4]);
                unsigned ah3 = __float_as_uint(Ah[base + 8 * SST + 4]);
                unsigned al0 = __float_as_uint(Al[base]);
                unsigned al1 = __float_as_uint(Al[base + 8 * SST]);
                unsigned al2 = __float_as_uint(Al[base + 4]);
                unsigned al3 = __float_as_uint(Al[base + 8 * SST + 4]);
#pragma unroll
                for (int nt = 0; nt < 4; nt++) {
                    mma8(acc[mt][nt], ah0, ah1, ah2, ah3, bh0[nt], bh1[nt]);
                    mma8(acc[mt][nt], ah0, ah1, ah2, ah3, bl0[nt], bl1[nt]);
                    mma8(acc[mt][nt], al0, al1, al2, al3, bh0[nt], bh1[nt]);
                }
            }
        }
        __syncthreads();
    }

#pragma unroll
    for (int nt = 0; nt < 4; nt++) {
        int cb = wn * 32 + nt * 8 + tg * 2;
        float bv0 = __ldg(bias + cb), bv1 = __ldg(bias + cb + 1);
        float sA = 0.f, sB = 0.f, qA = 0.f, qB = 0.f;
#pragma unroll
        for (int mt = 0; mt < 4; mt++) {
            int r0 = m0 + wm * 64 + mt * 16 + g;
            int r1 = r0 + 8;
            if (r0 < M) {
                float v0 = acc[mt][nt].x + bv0, v1 = acc[mt][nt].y + bv1;
                *(float2*)(C + (size_t)r0 * HD + cb) = make_float2(v0, v1);
                sA += v0; qA += v0 * v0; sB += v1; qB += v1 * v1;
            }
            if (r1 < M) {
                float v2 = acc[mt][nt].z + bv0, v3 = acc[mt][nt].w + bv1;
                *(float2*)(C + (size_t)r1 * HD + cb) = make_float2(v2, v3);
                sA += v2; qA += v2 * v2; sB += v3; qB += v3 * v3;
            }
        }
#pragma unroll
        for (int off = 4; off <= 16; off <<= 1) {
            sA += __shfl_xor_sync(0xffffffffu, sA, off);
            sB += __shfl_xor_sync(0xffffffffu, sB, off);
            qA += __shfl_xor_sync(0xffffffffu, qA, off);
            qB += __shfl_xor_sync(0xffffffffu, qB, off);
        }
        if (g == 0) {
            atomicAdd(stat + cb, sA);
            atomicAdd(stat + cb + 1, sB);
            atomicAdd(stat + 128 + cb, qA);
            atomicAdd(stat + 128 + cb + 1, qB);
        }
    }
}

// ---------------- batchnorm apply ----------------
__global__ void k_bnrelu(const float* __restrict__ in, const float* __restrict__ stat,
                         const float* __restrict__ gamma, const float* __restrict__ beta,
                         float* __restrict__ out, int M) {
    __shared__ float sc[128], sh[128];
    if (threadIdx.x < 128) {
        int c = threadIdx.x;
        float mean = stat[c] / (float)M;
        float var = stat[128 + c] / (float)M - mean * mean;
        float s = gamma[c] * rsqrtf(var + 1e-5f);
        sc[c] = s;
        sh[c] = beta[c] - mean * s;
    }
    __syncthreads();
    int total = M * 32;
    for (int i = blockIdx.x * blockDim.x + threadIdx.x; i < total;
         i += gridDim.x * blockDim.x) {
        int c = (i & 31) * 4;
        float4 v = ((const float4*)in)[i];
        v.x = fmaxf(0.f, v.x * sc[c + 0] + sh[c + 0]);
        v.y = fmaxf(0.f, v.y * sc[c + 1] + sh[c + 1]);
        v.z = fmaxf(0.f, v.z * sc[c + 2] + sh[c + 2]);
        v.w = fmaxf(0.f, v.w * sc[c + 3] + sh[c + 3]);
        ((float4*)out)[i] = v;
    }
}

// ---------------- fused LSTM cell ----------------
__global__ void __launch_bounds__(256) k_lstm(const float* __restrict__ X, int D,
                                              const float* __restrict__ hprev,
                                              const float* __restrict__ Wih,
                                              const float* __restrict__ Whh,
                                              const float* __restrict__ bias,
                                              const float* __restrict__ cprev,
                                              float* __restrict__ hout,
                                              float* __restrict__ cout) {
    __shared__ float Xs[32][16];
    __shared__ float Ws[32][68];
    int m0 = blockIdx.x * 16, c0 = blockIdx.y * 16;
    int t = threadIdx.x, ty = t >> 4, tx = t & 15;
    float acc[4] = {0.f, 0.f, 0.f, 0.f};
    int total = D + 128;
    for (int k0 = 0; k0 < total; k0 += 32) {
        const float* src; int sstride, kb;
        const float* w; int wstride;
        if (k0 < D) { src = X; sstride = D; kb = k0; w = Wih; wstride = D; }
        else { src = hprev; sstride = 128; kb = k0 - D; w = Whh; wstride = 128; }
#pragma unroll
        for (int u = 0; u < 2; u++) {
            int e = t + u * 256;
            int kk = e >> 4, mm = e & 15;
            Xs[kk][mm] = __ldg(src + (size_t)(m0 + mm) * sstride + kb + kk);
        }
#pragma unroll
        for (int u = 0; u < 8; u++) {
            int e = t + u * 256;
            int kk = e >> 6, nn = e & 63;
            int gg = nn >> 4, ci = nn & 15;
            Ws[kk][nn] = __ldg(w + (size_t)(gg * 128 + c0 + ci) * wstride + kb + kk);
        }
        __syncthreads();
#pragma unroll 8
        for (int kk = 0; kk < 32; kk++) {
            float a = Xs[kk][ty];
            acc[0] += a * Ws[kk][tx];
            acc[1] += a * Ws[kk][16 + tx];
            acc[2] += a * Ws[kk][32 + tx];
            acc[3] += a * Ws[kk][48 + tx];
        }
        __syncthreads();
    }
    int b = m0 + ty, c = c0 + tx;
    float gi = acc[0] + __ldg(bias + c);
    float gf = acc[1] + __ldg(bias + 128 + c);
    float gc = acc[2] + __ldg(bias + 256 + c);
    float go = acc[3] + __ldg(bias + 384 + c);
    int idx = b * HD + c;
    float si = 1.f / (1.f + __expf(-gi));
    float sf = 1.f / (1.f + __expf(-gf));
    float so = 1.f / (1.f + __expf(-go));
    float cn = sf * cprev[idx] + si * tanhf(gc);
    cout[idx] = cn;
    hout[idx] = so * tanhf(cn);
}

// ---------------- fused per-graph attention (+ optional final linear) ----------------
// one block per graph; batch sorted so nodes are contiguous [goff[b], goff[b+1])
__global__ void __launch_bounds__(256) k_attn(const float* __restrict__ xf,
                                              const float* __restrict__ q,
                                              float* __restrict__ qstar,
                                              const float* __restrict__ linW,
                                              const float* __restrict__ linb,
                                              float* __restrict__ out, int last) {
    __shared__ float se[SECAP];
    __shared__ float wmax[8];
    __shared__ float wsum[8];
    __shared__ float wr[8][132];
    int b = blockIdx.x;
    int t = threadIdx.x, w = t >> 5, lane = t & 31;
    int n0 = g_goff[b], n1 = g_goff[b + 1];
    int cnt = n1 - n0;
    const float4* x4 = (const float4*)xf;
    float4 qv = ((const float4*)(q + (size_t)b * HD))[lane];
    bool fits = (cnt <= SECAP);

    float mymax = -1e30f;
    for (int i = w; i < cnt; i += 8) {
        int n = n0 + i;
        float4 xv = x4[(size_t)n * 32 + lane];
        float d = xv.x * qv.x + xv.y * qv.y + xv.z * qv.z + xv.w * qv.w;
#pragma unroll
        for (int off = 16; off; off >>= 1) d += __shfl_xor_sync(0xffffffffu, d, off);
        if (fits && lane == 0) se[i] = d;
        mymax = fmaxf(mymax, d);
    }
    if (lane == 0) wmax[w] = mymax;
    __syncthreads();
    float m = -1e30f;
#pragma unroll
    for (int i = 0; i < 8; i++) m = fmaxf(m, wmax[i]);

    float4 racc = make_float4(0.f, 0.f, 0.f, 0.f);
    float ssum = 0.f;
    for (int i = w; i < cnt; i += 8) {
        int n = n0 + i;
        float4 xv = x4[(size_t)n * 32 + lane];
        float d;
        if (fits) d = se[i];
        else {
            d = xv.x * qv.x + xv.y * qv.y + xv.z * qv.z + xv.w * qv.w;
#pragma unroll
            for (int off = 16; off; off >>= 1) d += __shfl_xor_sync(0xffffffffu, d, off);
        }
        float ee = __expf(d - m);
        racc.x += ee * xv.x; racc.y += ee * xv.y;
        racc.z += ee * xv.z; racc.w += ee * xv.w;
        ssum += ee;
    }
    if (lane == 0) wsum[w] = ssum;
    *(float4*)&wr[w][lane * 4] = racc;
    __syncthreads();

    if (w == 0) {
        float4 rt = make_float4(0.f, 0.f, 0.f, 0.f);
        float st = 0.f;
#pragma unroll
        for (int i = 0; i < 8; i++) {
            float4 v = *(float4*)&wr[i][lane * 4];
            rt.x += v.x; rt.y += v.y; rt.z += v.z; rt.w += v.w;
            st += wsum[i];
        }
        float inv = (cnt > 0) ? 1.f / st : 0.f;
        rt.x *= inv; rt.y *= inv; rt.z *= inv; rt.w *= inv;
        *(float4*)(qstar + (size_t)b * 256 + 128 + lane * 4) = rt;
    } else if (w == 1) {
        *(float4*)(qstar + (size_t)b * 256 + lane * 4) = qv;
    }

    if (last) {
        __syncthreads();
        if (w < 2) {
            const float* qs = qstar + (size_t)b * 256;
            const float* wrow = linW + w * 256;
            float s = 0.f;
#pragma unroll
            for (int u = 0; u < 8; u++) {
                int k = lane + u * 32;
                s += qs[k] * __ldg(wrow + k);
            }
#pragma unroll
            for (int off = 16; off; off >>= 1) s += __shfl_xor_sync(0xffffffffu, s, off);
            if (lane == 0) out[b * 2 + w] = s + __ldg(linb + w);
        }
    }
}

// ---------------- host ----------------
static float* symf(const void* sym) {
    void* p = nullptr;
    cudaGetSymbolAddress(&p, sym);
    return (float*)p;
}

extern "C" void kernel_launch(void* const* d_in, const int* in_sizes, int n_in,
                              void* d_out, int out_size) {
    const float* x     = (const float*)d_in[0];
    const int*   ei    = (const int*)d_in[1];
    const int*   batch = (const int*)d_in[2];
    const float* gW1[2] = {(const float*)d_in[3],  (const float*)d_in[11]};
    const float* gb1[2] = {(const float*)d_in[4],  (const float*)d_in[12]};
    const float* gg1[2] = {(const float*)d_in[5],  (const float*)d_in[13]};
    const float* ge1[2] = {(const float*)d_in[6],  (const float*)d_in[14]};
    const float* gW2[2] = {(const float*)d_in[7],  (const float*)d_in[15]};
    const float* gb2[2] = {(const float*)d_in[8],  (const float*)d_in[16]};
    const float* gg2[2] = {(const float*)d_in[9],  (const float*)d_in[17]};
    const float* ge2[2] = {(const float*)d_in[10], (const float*)d_in[18]};
    const float* Wih0 = (const float*)d_in[19];
    const float* Whh0 = (const float*)d_in[20];
    const float* b0   = (const float*)d_in[21];
    const float* WihR = (const float*)d_in[22];
    const float* WhhR = (const float*)d_in[23];
    const float* bR   = (const float*)d_in[24];
    const float* linW = (const float*)d_in[25];
    const float* linb = (const float*)d_in[26];
    float* out = (float*)d_out;

    float* agg   = symf(g_agg);
    float* tmp   = symf(g_tmp);
    float* feat  = symf(g_feat);
    float* stats = symf(g_stats);
    float* hbuf  = symf(g_h);
    float* cbuf  = symf(g_c);
    float* qstar = symf(g_qstar);

    const int gemmSmem = 4 * 128 * SST * sizeof(float);
    cudaFuncSetAttribute(k_gemm_tf32, cudaFuncAttributeMaxDynamicSharedMemorySize,
                         gemmSmem);

    k_zero<<<256, 256>>>();
    k_goff<<<(NN + 255) / 256, 256>>>(batch);
    k_hist<<<(NE + 255) / 256, 256>>>(ei);
    k_scan1<<<SCB, 1024>>>();
    k_scan2<<<1, 64>>>();
    k_scan3<<<(NN + 255) / 256, 256>>>();
    k_scatter<<<(NE + 255) / 256, 256>>>(ei);

    int gemmBlocks = (NN + 127) / 128;
    int gatherBlocks = (NN * 32 + 255) / 256;

    const float* layerIn = x;
    for (int l = 0; l < 2; l++) {
        k_gather<<<gatherBlocks, 256>>>(layerIn, agg);
        float* st1 = stats + (l * 2 + 0) * 512;
        float* st2 = stats + (l * 2 + 1) * 512;
        k_gemm_tf32<<<gemmBlocks, 256, gemmSmem>>>(agg, gW1[l], gb1[l], tmp, st1, NN);
        k_bnrelu<<<2048, 256>>>(tmp, st1, gg1[l], ge1[l], tmp, NN);
        k_gemm_tf32<<<gemmBlocks, 256, gemmSmem>>>(tmp, gW2[l], gb2[l], agg, st2, NN);
        k_bnrelu<<<2048, 256>>>(agg, st2, gg2[l], ge2[l], feat, NN);
        layerIn = feat;
    }

    dim3 lstmGrid(BGR / 16, HD / 16);

    for (int s = 0; s < 4; s++) {
        int p = s & 1;
        float* hOld = hbuf + p * 4 * BH;
        float* hNew = hbuf + (p ^ 1) * 4 * BH;
        float* cOld = cbuf + p * 4 * BH;
        float* cNew = cbuf + (p ^ 1) * 4 * BH;
        for (int l = 0; l < 4; l++) {
            const float* X = (l == 0) ? qstar : (hNew + (l - 1) * BH);
            int D = (l == 0) ? 256 : 128;
            const float* Wih = (l == 0) ? Wih0 : (WihR + (size_t)(l - 1) * 512 * 128);
            const float* Whh = (l == 0) ? Whh0 : (WhhR + (size_t)(l - 1) * 512 * 128);
            const float* bb  = (l == 0) ? b0   : (bR + (size_t)(l - 1) * 512);
            k_lstm<<<lstmGrid, 256>>>(X, D, hOld + l * BH, Wih, Whh, bb,
                                      cOld + l * BH, hNew + l * BH, cNew + l * BH);
        }
        k_attn<<<BGR, 256>>>(feat, hNew + 3 * BH, qstar, linW, linb, out, s == 3);
    }
}